// round 2
// baseline (speedup 1.0000x reference)
#include <cuda_runtime.h>
#include <cuda_bf16.h>
#include <math.h>

// Problem constants
#define BB   2
#define LL   2048
#define DD   1024
#define DIM  2048      // d_inner
#define DS   16        // d_state
#define DTRK 64        // dt_rank
#define NXD  96        // DTR + 2*DS
#define BL   (BB*LL)   // 4096 rows

// ---------------- scratch (device globals; no runtime allocation) ----------
__device__ float g_h[(size_t)BL * DD];          // post-LN hidden
__device__ float g_xz[(size_t)BL * 2 * DIM];    // in_proj output (x_in | z)
__device__ float g_xc[(size_t)BL * DIM];        // conv+silu output
__device__ float g_xdbl[(size_t)BL * NXD];      // x_proj output (dt_r | B | C)
__device__ float g_dtraw[(size_t)BL * DIM];     // dt linear (pre bias/softplus)
__device__ float g_y[(size_t)BL * DIM];         // gated scan output

// ---------------- fused add + LayerNorm ------------------------------------
// row per block (B*L rows of D=1024), 256 threads, 1 float4/thread.
// Writes residual (second half of d_out) and normalized h.
__global__ __launch_bounds__(256) void addnorm_kernel(
    const float* __restrict__ x, const float* __restrict__ res,
    const float* __restrict__ w, const float* __restrict__ b,
    float* __restrict__ res_out, float* __restrict__ h_out)
{
    const int row = blockIdx.x;
    const int tid = threadIdx.x;
    const float4* xv = reinterpret_cast<const float4*>(x + (size_t)row * DD);
    const float4* rv = reinterpret_cast<const float4*>(res + (size_t)row * DD);
    float4 a = xv[tid], r = rv[tid];
    float4 v = make_float4(a.x + r.x, a.y + r.y, a.z + r.z, a.w + r.w);
    reinterpret_cast<float4*>(res_out + (size_t)row * DD)[tid] = v;

    float s  = v.x + v.y + v.z + v.w;
    float ss = v.x*v.x + v.y*v.y + v.z*v.z + v.w*v.w;
    __shared__ float red[16];
    #pragma unroll
    for (int o = 16; o > 0; o >>= 1) {
        s  += __shfl_xor_sync(0xFFFFFFFFu, s,  o);
        ss += __shfl_xor_sync(0xFFFFFFFFu, ss, o);
    }
    int wid = tid >> 5, lane = tid & 31;
    if (lane == 0) { red[wid] = s; red[8 + wid] = ss; }
    __syncthreads();
    if (tid == 0) {
        float ts = 0.f, tss = 0.f;
        #pragma unroll
        for (int i = 0; i < 8; i++) { ts += red[i]; tss += red[8 + i]; }
        float mean = ts * (1.f / DD);
        float var  = tss * (1.f / DD) - mean * mean;
        red[0] = mean;
        red[1] = rsqrtf(var + 1e-5f);
    }
    __syncthreads();
    float mean = red[0], rstd = red[1];
    float4 wv = reinterpret_cast<const float4*>(w)[tid];
    float4 bv = reinterpret_cast<const float4*>(b)[tid];
    float4 h;
    h.x = (v.x - mean) * rstd * wv.x + bv.x;
    h.y = (v.y - mean) * rstd * wv.y + bv.y;
    h.z = (v.z - mean) * rstd * wv.z + bv.z;
    h.w = (v.w - mean) * rstd * wv.w + bv.w;
    reinterpret_cast<float4*>(h_out + (size_t)row * DD)[tid] = h;
}

// ---------------- fp32 SGEMM, C[m][n] = sum_k A[m][k] * B[n][k] -------------
// 128x128x16 tiles, 256 threads, 8x8 micro-tile. N-dim guarded (for N=96).
// M must be a multiple of 128, K a multiple of 16 (true for all call sites).
__global__ __launch_bounds__(256) void sgemm_nt(
    const float* __restrict__ A, int lda,
    const float* __restrict__ B, int ldb,
    float* __restrict__ C, int ldc,
    int M, int N, int K)
{
    __shared__ float As[16][128];
    __shared__ float Bs[16][128];
    const int tid = threadIdx.x;
    const int m0 = blockIdx.y * 128;
    const int n0 = blockIdx.x * 128;
    const int tx = tid & 15;        // 16 cols of threads
    const int ty = tid >> 4;        // 16 rows of threads

    float acc[8][8];
    #pragma unroll
    for (int i = 0; i < 8; i++)
        #pragma unroll
        for (int j = 0; j < 8; j++) acc[i][j] = 0.f;

    for (int k0 = 0; k0 < K; k0 += 16) {
        // A tile: 128 rows x 16 k, 512 float4s / 256 threads
        #pragma unroll
        for (int i = 0; i < 2; i++) {
            int f = tid * 2 + i;
            int r = f >> 2;
            int c = (f & 3) << 2;
            float4 v = *reinterpret_cast<const float4*>(
                A + (size_t)(m0 + r) * lda + k0 + c);
            As[c + 0][r] = v.x; As[c + 1][r] = v.y;
            As[c + 2][r] = v.z; As[c + 3][r] = v.w;
        }
        // B tile (guard rows >= N)
        #pragma unroll
        for (int i = 0; i < 2; i++) {
            int f = tid * 2 + i;
            int r = f >> 2;
            int c = (f & 3) << 2;
            int n = n0 + r;
            float4 v = make_float4(0.f, 0.f, 0.f, 0.f);
            if (n < N)
                v = *reinterpret_cast<const float4*>(
                    B + (size_t)n * ldb + k0 + c);
            Bs[c + 0][r] = v.x; Bs[c + 1][r] = v.y;
            Bs[c + 2][r] = v.z; Bs[c + 3][r] = v.w;
        }
        __syncthreads();

        #pragma unroll
        for (int kk = 0; kk < 16; kk++) {
            float av[8], bv[8];
            #pragma unroll
            for (int i = 0; i < 8; i += 4) {
                float4 v = *reinterpret_cast<const float4*>(&As[kk][ty * 8 + i]);
                av[i] = v.x; av[i+1] = v.y; av[i+2] = v.z; av[i+3] = v.w;
            }
            #pragma unroll
            for (int j = 0; j < 8; j += 4) {
                float4 v = *reinterpret_cast<const float4*>(&Bs[kk][tx * 8 + j]);
                bv[j] = v.x; bv[j+1] = v.y; bv[j+2] = v.z; bv[j+3] = v.w;
            }
            #pragma unroll
            for (int i = 0; i < 8; i++)
                #pragma unroll
                for (int j = 0; j < 8; j++)
                    acc[i][j] = fmaf(av[i], bv[j], acc[i][j]);
        }
        __syncthreads();
    }

    #pragma unroll
    for (int i = 0; i < 8; i++) {
        int m = m0 + ty * 8 + i;
        #pragma unroll
        for (int j = 0; j < 8; j += 4) {
            int n = n0 + tx * 8 + j;
            if (n < N) {
                float4 v = make_float4(acc[i][j], acc[i][j+1], acc[i][j+2], acc[i][j+3]);
                *reinterpret_cast<float4*>(C + (size_t)m * ldc + n) = v;
            }
        }
    }
}

// ---------------- causal depthwise conv (DC=4) + SiLU -----------------------
__global__ __launch_bounds__(256) void conv_silu_kernel(
    const float* __restrict__ xz, const float* __restrict__ cw,
    const float* __restrict__ cb, float* __restrict__ xc)
{
    int idx = blockIdx.x * blockDim.x + threadIdx.x;    // over B*L*DIM
    if (idx >= BB * LL * DIM) return;
    int d = idx % DIM;
    int t = (idx / DIM) % LL;
    int b = idx / (DIM * LL);
    float w0 = cw[d * 4 + 0], w1 = cw[d * 4 + 1];
    float w2 = cw[d * 4 + 2], w3 = cw[d * 4 + 3];
    size_t base = ((size_t)(b * LL + t)) * (2 * DIM) + d;
    float acc = cb[d];
    if (t >= 3) acc = fmaf(xz[base - 3 * (size_t)(2 * DIM)], w0, acc);
    if (t >= 2) acc = fmaf(xz[base - 2 * (size_t)(2 * DIM)], w1, acc);
    if (t >= 1) acc = fmaf(xz[base - 1 * (size_t)(2 * DIM)], w2, acc);
    acc = fmaf(xz[base], w3, acc);
    float sg = 1.f / (1.f + __expf(-acc));
    xc[idx] = acc * sg;
}

// ---------------- selective scan (fused softplus, D-skip, SiLU gate) --------
// grid (DIM/128, B), 128 threads; thread owns one channel d, state in regs.
// B_t / C_t staged in shared in 32-step chunks.
#define CH 32
__global__ __launch_bounds__(128) void scan_kernel(
    const float* __restrict__ xdbl, const float* __restrict__ dtraw,
    const float* __restrict__ dtb, const float* __restrict__ xc,
    const float* __restrict__ xz, const float* __restrict__ A_log,
    const float* __restrict__ Dp, float* __restrict__ y_out)
{
    const int b = blockIdx.y;
    const int d = blockIdx.x * 128 + threadIdx.x;
    float a[DS], h[DS];
    #pragma unroll
    for (int s = 0; s < DS; s++) {
        a[s] = -__expf(A_log[(size_t)d * DS + s]);
        h[s] = 0.f;
    }
    const float Dd   = Dp[d];
    const float bias = dtb[d];

    __shared__ float sB[CH][DS];
    __shared__ float sC[CH][DS];

    for (int t0 = 0; t0 < LL; t0 += CH) {
        __syncthreads();
        for (int idx = threadIdx.x; idx < CH * 32; idx += 128) {
            int r = idx >> 5, c = idx & 31;
            float v = xdbl[(size_t)(b * LL + t0 + r) * NXD + DTRK + c];
            if (c < DS) sB[r][c] = v; else sC[r][c - DS] = v;
        }
        __syncthreads();

        #pragma unroll 4
        for (int r = 0; r < CH; r++) {
            int t = t0 + r;
            size_t off = (size_t)(b * LL + t) * DIM + d;
            float dtv = dtraw[off] + bias;
            dtv = (dtv > 20.f) ? dtv : log1pf(__expf(dtv));   // softplus
            float x = xc[off];
            float z = xz[(size_t)(b * LL + t) * (2 * DIM) + DIM + d];
            float dtx = dtv * x;
            float y = 0.f;
            #pragma unroll
            for (int s = 0; s < DS; s++) {
                float dA = __expf(dtv * a[s]);
                h[s] = fmaf(dA, h[s], dtx * sB[r][s]);
                y = fmaf(h[s], sC[r][s], y);
            }
            float sz = z / (1.f + __expf(-z));
            y_out[off] = (y + Dd * x) * sz;
        }
    }
}

// ---------------- launch ----------------------------------------------------
extern "C" void kernel_launch(void* const* d_in, const int* in_sizes, int n_in,
                              void* d_out, int out_size)
{
    const float* x          = (const float*)d_in[0];
    const float* residual   = (const float*)d_in[1];
    const float* ln_w       = (const float*)d_in[2];
    const float* ln_b       = (const float*)d_in[3];
    const float* in_proj_w  = (const float*)d_in[4];   // (2*DIM, D)
    const float* conv_w     = (const float*)d_in[5];   // (DIM, 4)
    const float* conv_b     = (const float*)d_in[6];
    const float* x_proj_w   = (const float*)d_in[7];   // (96, DIM)
    const float* dt_proj_w  = (const float*)d_in[8];   // (DIM, 64)
    const float* dt_proj_b  = (const float*)d_in[9];
    const float* A_log      = (const float*)d_in[10];  // (DIM, 16)
    const float* D_param    = (const float*)d_in[11];
    const float* out_proj_w = (const float*)d_in[12];  // (D, DIM)

    float* out     = (float*)d_out;                    // (B,L,D)
    float* res_out = out + (size_t)BL * DD;            // (B,L,D)

    float* h     = g_h;
    float* xz    = g_xz;
    float* xc    = g_xc;
    float* xdbl  = g_xdbl;
    float* dtraw = g_dtraw;
    float* y     = g_y;
    cudaGetSymbolAddress((void**)&h,     g_h);
    cudaGetSymbolAddress((void**)&xz,    g_xz);
    cudaGetSymbolAddress((void**)&xc,    g_xc);
    cudaGetSymbolAddress((void**)&xdbl,  g_xdbl);
    cudaGetSymbolAddress((void**)&dtraw, g_dtraw);
    cudaGetSymbolAddress((void**)&y,     g_y);

    // 1) residual = x + residual; h = LN(residual)
    addnorm_kernel<<<BL, 256>>>(x, residual, ln_w, ln_b, res_out, h);

    // 2) xz = h @ in_proj_w^T   (4096 x 4096 x 1024)
    sgemm_nt<<<dim3(2 * DIM / 128, BL / 128), 256>>>(
        h, DD, in_proj_w, DD, xz, 2 * DIM, BL, 2 * DIM, DD);

    // 3) xc = silu(causal_conv(x_in))
    conv_silu_kernel<<<(BB * LL * DIM + 255) / 256, 256>>>(xz, conv_w, conv_b, xc);

    // 4) x_dbl = xc @ x_proj_w^T   (4096 x 96 x 2048)
    sgemm_nt<<<dim3(1, BL / 128), 256>>>(
        xc, DIM, x_proj_w, DIM, xdbl, NXD, BL, NXD, DIM);

    // 5) dt_raw = dt_r @ dt_proj_w^T   (4096 x 2048 x 64), bias+softplus in scan
    sgemm_nt<<<dim3(DIM / 128, BL / 128), 256>>>(
        xdbl, NXD, dt_proj_w, DTRK, dtraw, DIM, BL, DIM, DTRK);

    // 6) selective scan + D-skip + SiLU(z) gating -> y
    scan_kernel<<<dim3(DIM / 128, BB), 128>>>(
        xdbl, dtraw, dt_proj_b, xc, xz, A_log, D_param, y);

    // 7) out = y @ out_proj_w^T   (4096 x 1024 x 2048)
    sgemm_nt<<<dim3(DD / 128, BL / 128), 256>>>(
        y, DIM, out_proj_w, DIM, out, DD, BL, DD, DIM);
}

// round 4
// speedup vs baseline: 1.3823x; 1.3823x over previous
#include <cuda_runtime.h>
#include <cuda_bf16.h>
#include <cstdint>
#include <math.h>

// Problem constants
#define BB   2
#define LL   2048
#define DD   1024
#define DIM  2048      // d_inner
#define DS   16        // d_state
#define DTRK 64        // dt_rank
#define NXD  96        // DTR + 2*DS
#define BL   (BB*LL)   // 4096 rows

// ---------------- scratch (device globals; no runtime allocation) ----------
__device__ __align__(256) float g_xz[(size_t)BL * 2 * DIM];
__device__ __align__(256) float g_xc[(size_t)BL * DIM];
__device__ __align__(256) float g_xdbl[(size_t)BL * NXD];
__device__ __align__(256) float g_dtraw[(size_t)BL * DIM];

__device__ __align__(256) __nv_bfloat16 g_h_hi[(size_t)BL * DD],    g_h_lo[(size_t)BL * DD];
__device__ __align__(256) __nv_bfloat16 g_wi_hi[(size_t)2*DIM*DD],  g_wi_lo[(size_t)2*DIM*DD];
__device__ __align__(256) __nv_bfloat16 g_xc_hi[(size_t)BL * DIM],  g_xc_lo[(size_t)BL * DIM];
__device__ __align__(256) __nv_bfloat16 g_xp_hi[(size_t)NXD * DIM], g_xp_lo[(size_t)NXD * DIM];
__device__ __align__(256) __nv_bfloat16 g_dta_hi[(size_t)BL * DTRK],g_dta_lo[(size_t)BL * DTRK];
__device__ __align__(256) __nv_bfloat16 g_dtw_hi[(size_t)DIM*DTRK], g_dtw_lo[(size_t)DIM*DTRK];
__device__ __align__(256) __nv_bfloat16 g_y_hi[(size_t)BL * DIM],   g_y_lo[(size_t)BL * DIM];
__device__ __align__(256) __nv_bfloat16 g_ow_hi[(size_t)DD * DIM],  g_ow_lo[(size_t)DD * DIM];

// ---------------- helpers ----------------------------------------------------
__device__ __forceinline__ uint32_t smem_u32(const void* p) {
    uint32_t a;
    asm("{ .reg .u64 t; cvta.to.shared.u64 t, %1; cvt.u32.u64 %0, t; }"
        : "=r"(a) : "l"(p));
    return a;
}
__device__ __forceinline__ void split_bf16(float v, __nv_bfloat16& hi, __nv_bfloat16& lo) {
    hi = __float2bfloat16(v);
    lo = __float2bfloat16(v - __bfloat162float(hi));
}

__device__ __forceinline__ void ldm_x4(uint32_t addr, uint32_t r[4]) {
    asm volatile("ldmatrix.sync.aligned.m8n8.x4.shared.b16 {%0,%1,%2,%3}, [%4];"
        : "=r"(r[0]), "=r"(r[1]), "=r"(r[2]), "=r"(r[3]) : "r"(addr));
}
__device__ __forceinline__ void mma_bf16(float d[4], const uint32_t a[4],
                                         uint32_t b0, uint32_t b1) {
    asm volatile(
        "mma.sync.aligned.m16n8k16.row.col.f32.bf16.bf16.f32 "
        "{%0,%1,%2,%3}, {%4,%5,%6,%7}, {%8,%9}, {%0,%1,%2,%3};"
        : "+f"(d[0]), "+f"(d[1]), "+f"(d[2]), "+f"(d[3])
        : "r"(a[0]), "r"(a[1]), "r"(a[2]), "r"(a[3]), "r"(b0), "r"(b1));
}
__device__ __forceinline__ void cp16(uint32_t dst, const void* src, int srcsize) {
    asm volatile("cp.async.cg.shared.global [%0], [%1], 16, %2;"
                 :: "r"(dst), "l"(src), "r"(srcsize));
}
__device__ __forceinline__ void cp_commit() {
    asm volatile("cp.async.commit_group;");
}
__device__ __forceinline__ void cp_wait1() {
    asm volatile("cp.async.wait_group 1;");
}

// ---------------- split-bf16 tensor-core GEMM (mma.sync path) ----------------
// C[m][n] = sum_k A[m][k]*B[n][k]; A,B as bf16 hi/lo pairs (both K-contiguous).
// 128x128 CTA tile, BK=32, 8 warps (4m x 2n), warp tile 32x64.
// M % 128 == 0, K % 32 == 0; N guarded (zero-fill loads, guarded stores).
#define SKH   40                  // smem row stride in halves (64B data + 16B pad)
#define SKB   80                  // stride bytes
#define TILEB (128 * SKB)         // 10240 B per operand tile
#define STAGEB (4 * TILEB)        // 40960 B per stage
#define GSMEM (2 * STAGEB)        // 81920 B dynamic smem

__global__ __launch_bounds__(256, 1) void tc_gemm(
    const __nv_bfloat16* __restrict__ Ahi, const __nv_bfloat16* __restrict__ Alo,
    const __nv_bfloat16* __restrict__ Bhi, const __nv_bfloat16* __restrict__ Blo,
    float* __restrict__ C, int ldc, int N, int K)
{
    extern __shared__ char smem[];
    const uint32_t sbase = smem_u32(smem);
    const int tid  = threadIdx.x;
    const int wid  = tid >> 5;
    const int lane = tid & 31;
    const int warp_m = wid & 3;          // 0..3  -> 32-row slice
    const int warp_n = wid >> 2;         // 0..1  -> 64-col slice
    const int m0 = blockIdx.y * 128;
    const int n0 = blockIdx.x * 128;

    const __nv_bfloat16* srcA[2] = { Ahi + (size_t)m0 * K, Alo + (size_t)m0 * K };
    const __nv_bfloat16* srcB[2] = { Bhi + (size_t)n0 * K, Blo + (size_t)n0 * K };

    float acc[2][8][4];
    #pragma unroll
    for (int a = 0; a < 2; a++)
        #pragma unroll
        for (int b = 0; b < 8; b++)
            #pragma unroll
            for (int c = 0; c < 4; c++) acc[a][b][c] = 0.f;

    const int nch = K / 32;

    // ---- async load of one 4-tile chunk into a stage ----
    auto load_chunk = [&](int stage, int k0) {
        const uint32_t base = sbase + stage * STAGEB;
        #pragma unroll
        for (int i = 0; i < 8; i++) {
            const int tile = i >> 1;                 // 0..3 (constant per i)
            const int rem  = ((i & 1) << 8) + tid;   // 0..511
            const int row  = rem >> 2;
            const int c    = rem & 3;
            const uint32_t dst = base + tile * TILEB + row * SKB + c * 16;
            const __nv_bfloat16* g;
            int sz = 16;
            if (tile < 2) {
                g = srcA[tile] + (size_t)row * K + k0 + c * 8;
            } else {
                g = srcB[tile - 2] + (size_t)row * K + k0 + c * 8;
                if (n0 + row >= N) sz = 0;           // zero-fill OOB B rows
            }
            cp16(dst, g, sz);
        }
    };

    load_chunk(0, 0);
    cp_commit();

    for (int ch = 0; ch < nch; ch++) {
        if (ch + 1 < nch) load_chunk((ch + 1) & 1, (ch + 1) * 32);
        cp_commit();
        cp_wait1();
        __syncthreads();

        const uint32_t st = sbase + (ch & 1) * STAGEB;
        const uint32_t aHiB = st;
        const uint32_t aLoB = st + TILEB;
        const uint32_t bHiB = st + 2 * TILEB;
        const uint32_t bLoB = st + 3 * TILEB;

        #pragma unroll
        for (int k16 = 0; k16 < 2; k16++) {
            const int kcol = k16 * 16 + (lane >> 4) * 8;     // halves
            uint32_t ahi[2][4], alo[2][4];
            #pragma unroll
            for (int mf = 0; mf < 2; mf++) {
                const int row = warp_m * 32 + mf * 16 + (lane & 15);
                const uint32_t off = row * SKB + kcol * 2;
                ldm_x4(aHiB + off, ahi[mf]);
                ldm_x4(aLoB + off, alo[mf]);
            }
            #pragma unroll
            for (int nb = 0; nb < 4; nb++) {
                const int rowb = warp_n * 64 + nb * 16 + (lane & 15);
                const uint32_t offb = rowb * SKB + kcol * 2;
                uint32_t bh[4], bl[4];
                ldm_x4(bHiB + offb, bh);
                ldm_x4(bLoB + offb, bl);
                #pragma unroll
                for (int mf = 0; mf < 2; mf++) {
                    float* d0 = acc[mf][nb * 2];
                    float* d1 = acc[mf][nb * 2 + 1];
                    mma_bf16(d0, ahi[mf], bh[0], bh[2]);
                    mma_bf16(d1, ahi[mf], bh[1], bh[3]);
                    mma_bf16(d0, ahi[mf], bl[0], bl[2]);
                    mma_bf16(d1, ahi[mf], bl[1], bl[3]);
                    mma_bf16(d0, alo[mf], bh[0], bh[2]);
                    mma_bf16(d1, alo[mf], bh[1], bh[3]);
                }
            }
        }
        __syncthreads();
    }

    // ---- epilogue: fp32 stores, col-guarded ----
    #pragma unroll
    for (int mf = 0; mf < 2; mf++) {
        #pragma unroll
        for (int nf = 0; nf < 8; nf++) {
            const int r0  = m0 + warp_m * 32 + mf * 16 + (lane >> 2);
            const int col = n0 + warp_n * 64 + nf * 8 + (lane & 3) * 2;
            if (col < N) {
                float2 v0 = make_float2(acc[mf][nf][0], acc[mf][nf][1]);
                float2 v1 = make_float2(acc[mf][nf][2], acc[mf][nf][3]);
                *reinterpret_cast<float2*>(C + (size_t)r0 * ldc + col) = v0;
                *reinterpret_cast<float2*>(C + (size_t)(r0 + 8) * ldc + col) = v1;
            }
        }
    }
}

// ---------------- fp32 -> (hi,lo) conversion, strided source -----------------
__global__ __launch_bounds__(256) void cvt_pair_kernel(
    const float* __restrict__ src, int lds, int cols, long total,
    __nv_bfloat16* __restrict__ hi, __nv_bfloat16* __restrict__ lo)
{
    long i = (long)blockIdx.x * blockDim.x + threadIdx.x;
    if (i >= total) return;
    long r = i / cols, c = i % cols;
    float v = src[r * lds + c];
    __nv_bfloat16 h, l; split_bf16(v, h, l);
    hi[i] = h; lo[i] = l;
}

// ---------------- fused add + LayerNorm (emits residual + h hi/lo) ----------
__global__ __launch_bounds__(256) void addnorm_kernel(
    const float* __restrict__ x, const float* __restrict__ res,
    const float* __restrict__ w, const float* __restrict__ b,
    float* __restrict__ res_out,
    __nv_bfloat16* __restrict__ h_hi, __nv_bfloat16* __restrict__ h_lo)
{
    const int row = blockIdx.x;
    const int tid = threadIdx.x;
    const float4* xv = reinterpret_cast<const float4*>(x + (size_t)row * DD);
    const float4* rv = reinterpret_cast<const float4*>(res + (size_t)row * DD);
    float4 a = xv[tid], r = rv[tid];
    float4 v = make_float4(a.x + r.x, a.y + r.y, a.z + r.z, a.w + r.w);
    reinterpret_cast<float4*>(res_out + (size_t)row * DD)[tid] = v;

    float s  = v.x + v.y + v.z + v.w;
    float ss = v.x*v.x + v.y*v.y + v.z*v.z + v.w*v.w;
    __shared__ float red[16];
    #pragma unroll
    for (int o = 16; o > 0; o >>= 1) {
        s  += __shfl_xor_sync(0xFFFFFFFFu, s,  o);
        ss += __shfl_xor_sync(0xFFFFFFFFu, ss, o);
    }
    int wid = tid >> 5, lane = tid & 31;
    if (lane == 0) { red[wid] = s; red[8 + wid] = ss; }
    __syncthreads();
    if (tid == 0) {
        float ts = 0.f, tss = 0.f;
        #pragma unroll
        for (int i = 0; i < 8; i++) { ts += red[i]; tss += red[8 + i]; }
        float mean = ts * (1.f / DD);
        float var  = tss * (1.f / DD) - mean * mean;
        red[0] = mean; red[1] = rsqrtf(var + 1e-5f);
    }
    __syncthreads();
    float mean = red[0], rstd = red[1];
    float4 wv = reinterpret_cast<const float4*>(w)[tid];
    float4 bv = reinterpret_cast<const float4*>(b)[tid];
    float hv[4];
    hv[0] = (v.x - mean) * rstd * wv.x + bv.x;
    hv[1] = (v.y - mean) * rstd * wv.y + bv.y;
    hv[2] = (v.z - mean) * rstd * wv.z + bv.z;
    hv[3] = (v.w - mean) * rstd * wv.w + bv.w;
    __nv_bfloat16 hh[4], ll[4];
    #pragma unroll
    for (int i = 0; i < 4; i++) split_bf16(hv[i], hh[i], ll[i]);
    size_t o = (size_t)row * DD + tid * 4;
    *reinterpret_cast<uint2*>(h_hi + o) = *reinterpret_cast<uint2*>(hh);
    *reinterpret_cast<uint2*>(h_lo + o) = *reinterpret_cast<uint2*>(ll);
}

// ---------------- causal depthwise conv (DC=4) + SiLU ------------------------
__global__ __launch_bounds__(256) void conv_silu_kernel(
    const float* __restrict__ xz, const float* __restrict__ cw,
    const float* __restrict__ cb, float* __restrict__ xc,
    __nv_bfloat16* __restrict__ xc_hi, __nv_bfloat16* __restrict__ xc_lo)
{
    int idx = blockIdx.x * blockDim.x + threadIdx.x;
    if (idx >= BB * LL * DIM) return;
    int d = idx % DIM;
    int t = (idx / DIM) % LL;
    int b = idx / (DIM * LL);
    float w0 = cw[d * 4 + 0], w1 = cw[d * 4 + 1];
    float w2 = cw[d * 4 + 2], w3 = cw[d * 4 + 3];
    size_t base = ((size_t)(b * LL + t)) * (2 * DIM) + d;
    float acc = cb[d];
    if (t >= 3) acc = fmaf(xz[base - 3 * (size_t)(2 * DIM)], w0, acc);
    if (t >= 2) acc = fmaf(xz[base - 2 * (size_t)(2 * DIM)], w1, acc);
    if (t >= 1) acc = fmaf(xz[base - 1 * (size_t)(2 * DIM)], w2, acc);
    acc = fmaf(xz[base], w3, acc);
    float sg = 1.f / (1.f + __expf(-acc));
    float v = acc * sg;
    xc[idx] = v;
    __nv_bfloat16 h, l; split_bf16(v, h, l);
    xc_hi[idx] = h; xc_lo[idx] = l;
}

// ---------------- selective scan (fused softplus, D-skip, SiLU gate) ---------
#define CH 32
__global__ __launch_bounds__(128) void scan_kernel(
    const float* __restrict__ xdbl, const float* __restrict__ dtraw,
    const float* __restrict__ dtb, const float* __restrict__ xc,
    const float* __restrict__ xz, const float* __restrict__ A_log,
    const float* __restrict__ Dp,
    __nv_bfloat16* __restrict__ y_hi, __nv_bfloat16* __restrict__ y_lo)
{
    const int b = blockIdx.y;
    const int d = blockIdx.x * 128 + threadIdx.x;
    float a[DS], h[DS];
    #pragma unroll
    for (int s = 0; s < DS; s++) {
        a[s] = -__expf(A_log[(size_t)d * DS + s]);
        h[s] = 0.f;
    }
    const float Dd   = Dp[d];
    const float bias = dtb[d];

    __shared__ float sB[CH][DS];
    __shared__ float sC[CH][DS];

    for (int t0 = 0; t0 < LL; t0 += CH) {
        __syncthreads();
        for (int idx = threadIdx.x; idx < CH * 32; idx += 128) {
            int r = idx >> 5, c = idx & 31;
            float v = xdbl[(size_t)(b * LL + t0 + r) * NXD + DTRK + c];
            if (c < DS) sB[r][c] = v; else sC[r][c - DS] = v;
        }
        __syncthreads();

        #pragma unroll 4
        for (int r = 0; r < CH; r++) {
            int t = t0 + r;
            size_t off = (size_t)(b * LL + t) * DIM + d;
            float dtv = dtraw[off] + bias;
            dtv = (dtv > 20.f) ? dtv : log1pf(__expf(dtv));
            float x = xc[off];
            float z = xz[(size_t)(b * LL + t) * (2 * DIM) + DIM + d];
            float dtx = dtv * x;
            float y = 0.f;
            #pragma unroll
            for (int s = 0; s < DS; s++) {
                float dA = __expf(dtv * a[s]);
                h[s] = fmaf(dA, h[s], dtx * sB[r][s]);
                y = fmaf(h[s], sC[r][s], y);
            }
            float sz = z / (1.f + __expf(-z));
            float yo = (y + Dd * x) * sz;
            __nv_bfloat16 hh, ll; split_bf16(yo, hh, ll);
            y_hi[off] = hh; y_lo[off] = ll;
        }
    }
}

// ---------------- launch ------------------------------------------------------
extern "C" void kernel_launch(void* const* d_in, const int* in_sizes, int n_in,
                              void* d_out, int out_size)
{
    const float* x          = (const float*)d_in[0];
    const float* residual   = (const float*)d_in[1];
    const float* ln_w       = (const float*)d_in[2];
    const float* ln_b       = (const float*)d_in[3];
    const float* in_proj_w  = (const float*)d_in[4];   // (2*DIM, D)
    const float* conv_w     = (const float*)d_in[5];   // (DIM, 4)
    const float* conv_b     = (const float*)d_in[6];
    const float* x_proj_w   = (const float*)d_in[7];   // (96, DIM)
    const float* dt_proj_w  = (const float*)d_in[8];   // (DIM, 64)
    const float* dt_proj_b  = (const float*)d_in[9];
    const float* A_log      = (const float*)d_in[10];  // (DIM, 16)
    const float* D_param    = (const float*)d_in[11];
    const float* out_proj_w = (const float*)d_in[12];  // (D, DIM)

    float* out     = (float*)d_out;                    // (B,L,D)
    float* res_out = out + (size_t)BL * DD;            // (B,L,D)

    float *xz, *xc, *xdbl, *dtraw;
    __nv_bfloat16 *h_hi, *h_lo, *wi_hi, *wi_lo, *xc_hi, *xc_lo, *xp_hi, *xp_lo;
    __nv_bfloat16 *dta_hi, *dta_lo, *dtw_hi, *dtw_lo, *y_hi, *y_lo, *ow_hi, *ow_lo;
    cudaGetSymbolAddress((void**)&xz,    g_xz);
    cudaGetSymbolAddress((void**)&xc,    g_xc);
    cudaGetSymbolAddress((void**)&xdbl,  g_xdbl);
    cudaGetSymbolAddress((void**)&dtraw, g_dtraw);
    cudaGetSymbolAddress((void**)&h_hi,  g_h_hi);  cudaGetSymbolAddress((void**)&h_lo,  g_h_lo);
    cudaGetSymbolAddress((void**)&wi_hi, g_wi_hi); cudaGetSymbolAddress((void**)&wi_lo, g_wi_lo);
    cudaGetSymbolAddress((void**)&xc_hi, g_xc_hi); cudaGetSymbolAddress((void**)&xc_lo, g_xc_lo);
    cudaGetSymbolAddress((void**)&xp_hi, g_xp_hi); cudaGetSymbolAddress((void**)&xp_lo, g_xp_lo);
    cudaGetSymbolAddress((void**)&dta_hi,g_dta_hi);cudaGetSymbolAddress((void**)&dta_lo,g_dta_lo);
    cudaGetSymbolAddress((void**)&dtw_hi,g_dtw_hi);cudaGetSymbolAddress((void**)&dtw_lo,g_dtw_lo);
    cudaGetSymbolAddress((void**)&y_hi,  g_y_hi);  cudaGetSymbolAddress((void**)&y_lo,  g_y_lo);
    cudaGetSymbolAddress((void**)&ow_hi, g_ow_hi); cudaGetSymbolAddress((void**)&ow_lo, g_ow_lo);

    cudaFuncSetAttribute(tc_gemm, cudaFuncAttributeMaxDynamicSharedMemorySize, GSMEM);

    // weight conversions (independent of activations)
    {
        long t1 = (long)2 * DIM * DD;
        cvt_pair_kernel<<<(int)((t1 + 255) / 256), 256>>>(in_proj_w, DD, DD, t1, wi_hi, wi_lo);
        long t2 = (long)NXD * DIM;
        cvt_pair_kernel<<<(int)((t2 + 255) / 256), 256>>>(x_proj_w, DIM, DIM, t2, xp_hi, xp_lo);
        long t3 = (long)DIM * DTRK;
        cvt_pair_kernel<<<(int)((t3 + 255) / 256), 256>>>(dt_proj_w, DTRK, DTRK, t3, dtw_hi, dtw_lo);
        long t4 = (long)DD * DIM;
        cvt_pair_kernel<<<(int)((t4 + 255) / 256), 256>>>(out_proj_w, DIM, DIM, t4, ow_hi, ow_lo);
    }

    // 1) residual = x + residual; h = LN(residual) -> hi/lo
    addnorm_kernel<<<BL, 256>>>(x, residual, ln_w, ln_b, res_out, h_hi, h_lo);

    // 2) xz = h @ in_proj_w^T   (M=4096, N=4096, K=1024)
    tc_gemm<<<dim3(2 * DIM / 128, BL / 128), 256, GSMEM>>>(
        h_hi, h_lo, wi_hi, wi_lo, xz, 2 * DIM, 2 * DIM, DD);

    // 3) xc = silu(causal_conv(x_in))
    conv_silu_kernel<<<(BB * LL * DIM + 255) / 256, 256>>>(xz, conv_w, conv_b, xc, xc_hi, xc_lo);

    // 4) x_dbl = xc @ x_proj_w^T   (M=4096, N=96, K=2048)
    tc_gemm<<<dim3(1, BL / 128), 256, GSMEM>>>(
        xc_hi, xc_lo, xp_hi, xp_lo, xdbl, NXD, NXD, DIM);

    // 4b) convert dt_r slice of xdbl (cols 0..63) to pair
    {
        long t = (long)BL * DTRK;
        cvt_pair_kernel<<<(int)((t + 255) / 256), 256>>>(xdbl, NXD, DTRK, t, dta_hi, dta_lo);
    }

    // 5) dt_raw = dt_r @ dt_proj_w^T   (M=4096, N=2048, K=64)
    tc_gemm<<<dim3(DIM / 128, BL / 128), 256, GSMEM>>>(
        dta_hi, dta_lo, dtw_hi, dtw_lo, dtraw, DIM, DIM, DTRK);

    // 6) selective scan -> y hi/lo
    scan_kernel<<<dim3(DIM / 128, BB), 128>>>(
        xdbl, dtraw, dt_proj_b, xc, xz, A_log, D_param, y_hi, y_lo);

    // 7) out = y @ out_proj_w^T   (M=4096, N=1024, K=2048)
    tc_gemm<<<dim3(DD / 128, BL / 128), 256, GSMEM>>>(
        y_hi, y_lo, ow_hi, ow_lo, out, DD, DD, DIM);
}

// round 6
// speedup vs baseline: 1.3877x; 1.0039x over previous
#include <cuda_runtime.h>
#include <cuda_bf16.h>
#include <cstdint>
#include <math.h>

// Problem constants
#define BB   2
#define LL   2048
#define DD   1024
#define DIM  2048      // d_inner
#define DS   16        // d_state
#define DTRK 64        // dt_rank
#define NXD  96        // DTR + 2*DS
#define BL   (BB*LL)   // 4096 rows

// ---------------- scratch (device globals; no runtime allocation) ----------
__device__ __align__(256) float g_xz[(size_t)BL * 2 * DIM];
__device__ __align__(256) float g_xc[(size_t)BL * DIM];
__device__ __align__(256) float g_xdbl[(size_t)BL * NXD];
__device__ __align__(256) float g_dtraw[(size_t)BL * DIM];

__device__ __align__(256) __nv_bfloat16 g_h_hi[(size_t)BL * DD],    g_h_lo[(size_t)BL * DD];
__device__ __align__(256) __nv_bfloat16 g_wi_hi[(size_t)2*DIM*DD],  g_wi_lo[(size_t)2*DIM*DD];
__device__ __align__(256) __nv_bfloat16 g_xc_hi[(size_t)BL * DIM],  g_xc_lo[(size_t)BL * DIM];
__device__ __align__(256) __nv_bfloat16 g_xp_hi[(size_t)NXD * DIM], g_xp_lo[(size_t)NXD * DIM];
__device__ __align__(256) __nv_bfloat16 g_dta_hi[(size_t)BL * DTRK],g_dta_lo[(size_t)BL * DTRK];
__device__ __align__(256) __nv_bfloat16 g_dtw_hi[(size_t)DIM*DTRK], g_dtw_lo[(size_t)DIM*DTRK];
__device__ __align__(256) __nv_bfloat16 g_y_hi[(size_t)BL * DIM],   g_y_lo[(size_t)BL * DIM];
__device__ __align__(256) __nv_bfloat16 g_ow_hi[(size_t)DD * DIM],  g_ow_lo[(size_t)DD * DIM];

// ---------------- helpers ----------------------------------------------------
__device__ __forceinline__ uint32_t smem_u32(const void* p) {
    uint32_t a;
    asm("{ .reg .u64 t; cvta.to.shared.u64 t, %1; cvt.u32.u64 %0, t; }"
        : "=r"(a) : "l"(p));
    return a;
}
__device__ __forceinline__ void split_bf16(float v, __nv_bfloat16& hi, __nv_bfloat16& lo) {
    hi = __float2bfloat16(v);
    lo = __float2bfloat16(v - __bfloat162float(hi));
}

__device__ __forceinline__ void ldm_x4(uint32_t addr, uint32_t r[4]) {
    asm volatile("ldmatrix.sync.aligned.m8n8.x4.shared.b16 {%0,%1,%2,%3}, [%4];"
        : "=r"(r[0]), "=r"(r[1]), "=r"(r[2]), "=r"(r[3]) : "r"(addr));
}
__device__ __forceinline__ void mma_bf16(float d[4], const uint32_t a[4],
                                         uint32_t b0, uint32_t b1) {
    asm volatile(
        "mma.sync.aligned.m16n8k16.row.col.f32.bf16.bf16.f32 "
        "{%0,%1,%2,%3}, {%4,%5,%6,%7}, {%8,%9}, {%0,%1,%2,%3};"
        : "+f"(d[0]), "+f"(d[1]), "+f"(d[2]), "+f"(d[3])
        : "r"(a[0]), "r"(a[1]), "r"(a[2]), "r"(a[3]), "r"(b0), "r"(b1));
}
__device__ __forceinline__ void cp16(uint32_t dst, const void* src, int srcsize) {
    asm volatile("cp.async.cg.shared.global [%0], [%1], 16, %2;"
                 :: "r"(dst), "l"(src), "r"(srcsize));
}
__device__ __forceinline__ void cp_commit() {
    asm volatile("cp.async.commit_group;");
}
__device__ __forceinline__ void cp_wait1() {
    asm volatile("cp.async.wait_group 1;");
}

// ---------------- split-bf16 tensor-core GEMM (mma.sync path) ----------------
// C[m][n] = sum_k A[m][k]*B[n][k]; A,B as bf16 hi/lo pairs (both K-contiguous).
// 128x128 CTA tile, BK=32, 8 warps (4m x 2n), warp tile 32x64.
// MMAs grouped by split-term so same-accumulator reuse distance = 16 instrs
// (hides HMMA latency; the round-4 version stalled on RAW at distance 2).
#define SKH   40
#define SKB   80
#define TILEB (128 * SKB)         // 10240 B per operand tile
#define STAGEB (4 * TILEB)        // 40960 B per stage
#define GSMEM (2 * STAGEB)        // 81920 B dynamic smem

__global__ __launch_bounds__(256, 1) void tc_gemm(
    const __nv_bfloat16* __restrict__ Ahi, const __nv_bfloat16* __restrict__ Alo,
    const __nv_bfloat16* __restrict__ Bhi, const __nv_bfloat16* __restrict__ Blo,
    float* __restrict__ C, int ldc, int N, int K,
    __nv_bfloat16* __restrict__ Ehi, __nv_bfloat16* __restrict__ Elo, int ecols)
{
    extern __shared__ char smem[];
    const uint32_t sbase = smem_u32(smem);
    const int tid  = threadIdx.x;
    const int wid  = tid >> 5;
    const int lane = tid & 31;
    const int warp_m = wid & 3;
    const int warp_n = wid >> 2;
    const int m0 = blockIdx.y * 128;
    const int n0 = blockIdx.x * 128;

    const __nv_bfloat16* srcA[2] = { Ahi + (size_t)m0 * K, Alo + (size_t)m0 * K };
    const __nv_bfloat16* srcB[2] = { Bhi + (size_t)n0 * K, Blo + (size_t)n0 * K };

    float acc[2][8][4];
    #pragma unroll
    for (int a = 0; a < 2; a++)
        #pragma unroll
        for (int b = 0; b < 8; b++)
            #pragma unroll
            for (int c = 0; c < 4; c++) acc[a][b][c] = 0.f;

    const int nch = K / 32;

    auto load_chunk = [&](int stage, int k0) {
        const uint32_t base = sbase + stage * STAGEB;
        #pragma unroll
        for (int i = 0; i < 8; i++) {
            const int tile = i >> 1;
            const int rem  = ((i & 1) << 8) + tid;
            const int row  = rem >> 2;
            const int c    = rem & 3;
            const uint32_t dst = base + tile * TILEB + row * SKB + c * 16;
            const __nv_bfloat16* g;
            int sz = 16;
            if (tile < 2) {
                g = srcA[tile] + (size_t)row * K + k0 + c * 8;
            } else {
                g = srcB[tile - 2] + (size_t)row * K + k0 + c * 8;
                if (n0 + row >= N) sz = 0;
            }
            cp16(dst, g, sz);
        }
    };

    load_chunk(0, 0);
    cp_commit();

    for (int ch = 0; ch < nch; ch++) {
        if (ch + 1 < nch) load_chunk((ch + 1) & 1, (ch + 1) * 32);
        cp_commit();
        cp_wait1();
        __syncthreads();

        const uint32_t st = sbase + (ch & 1) * STAGEB;
        const uint32_t aHiB = st;
        const uint32_t aLoB = st + TILEB;
        const uint32_t bHiB = st + 2 * TILEB;
        const uint32_t bLoB = st + 3 * TILEB;

        #pragma unroll
        for (int k16 = 0; k16 < 2; k16++) {
            const int kcol = k16 * 16 + (lane >> 4) * 8;
            uint32_t ah[2][4], al[2][4], bh[4][4], bl[4][4];
            #pragma unroll
            for (int mf = 0; mf < 2; mf++) {
                const int row = warp_m * 32 + mf * 16 + (lane & 15);
                const uint32_t off = row * SKB + kcol * 2;
                ldm_x4(aHiB + off, ah[mf]);
                ldm_x4(aLoB + off, al[mf]);
            }
            #pragma unroll
            for (int nb = 0; nb < 4; nb++) {
                const int rowb = warp_n * 64 + nb * 16 + (lane & 15);
                const uint32_t offb = rowb * SKB + kcol * 2;
                ldm_x4(bHiB + offb, bh[nb]);
                ldm_x4(bLoB + offb, bl[nb]);
            }
            // term 1: Ahi * Bhi  (16 independent MMAs)
            #pragma unroll
            for (int mf = 0; mf < 2; mf++)
                #pragma unroll
                for (int nb = 0; nb < 4; nb++) {
                    mma_bf16(acc[mf][nb*2],   ah[mf], bh[nb][0], bh[nb][2]);
                    mma_bf16(acc[mf][nb*2+1], ah[mf], bh[nb][1], bh[nb][3]);
                }
            // term 2: Ahi * Blo
            #pragma unroll
            for (int mf = 0; mf < 2; mf++)
                #pragma unroll
                for (int nb = 0; nb < 4; nb++) {
                    mma_bf16(acc[mf][nb*2],   ah[mf], bl[nb][0], bl[nb][2]);
                    mma_bf16(acc[mf][nb*2+1], ah[mf], bl[nb][1], bl[nb][3]);
                }
            // term 3: Alo * Bhi
            #pragma unroll
            for (int mf = 0; mf < 2; mf++)
                #pragma unroll
                for (int nb = 0; nb < 4; nb++) {
                    mma_bf16(acc[mf][nb*2],   al[mf], bh[nb][0], bh[nb][2]);
                    mma_bf16(acc[mf][nb*2+1], al[mf], bh[nb][1], bh[nb][3]);
                }
        }
        __syncthreads();
    }

    // ---- epilogue: fp32 stores (col-guarded); optional bf16 pair emit -------
    #pragma unroll
    for (int mf = 0; mf < 2; mf++) {
        #pragma unroll
        for (int nf = 0; nf < 8; nf++) {
            const int r0  = m0 + warp_m * 32 + mf * 16 + (lane >> 2);
            const int col = n0 + warp_n * 64 + nf * 8 + (lane & 3) * 2;
            if (col < N) {
                float2 v0 = make_float2(acc[mf][nf][0], acc[mf][nf][1]);
                float2 v1 = make_float2(acc[mf][nf][2], acc[mf][nf][3]);
                *reinterpret_cast<float2*>(C + (size_t)r0 * ldc + col) = v0;
                *reinterpret_cast<float2*>(C + (size_t)(r0 + 8) * ldc + col) = v1;
                if (Ehi && col < ecols) {
                    __nv_bfloat16 h0, l0, h1, l1;
                    split_bf16(v0.x, h0, l0); split_bf16(v0.y, h1, l1);
                    __nv_bfloat162 hh = __nv_bfloat162(h0, h1);
                    __nv_bfloat162 ll = __nv_bfloat162(l0, l1);
                    *reinterpret_cast<__nv_bfloat162*>(Ehi + (size_t)r0 * ecols + col) = hh;
                    *reinterpret_cast<__nv_bfloat162*>(Elo + (size_t)r0 * ecols + col) = ll;
                    split_bf16(v1.x, h0, l0); split_bf16(v1.y, h1, l1);
                    hh = __nv_bfloat162(h0, h1); ll = __nv_bfloat162(l0, l1);
                    *reinterpret_cast<__nv_bfloat162*>(Ehi + (size_t)(r0+8) * ecols + col) = hh;
                    *reinterpret_cast<__nv_bfloat162*>(Elo + (size_t)(r0+8) * ecols + col) = ll;
                }
            }
        }
    }
}

// ---------------- weight conversions ----------------------------------------
__global__ __launch_bounds__(256) void cvt_flat_kernel(
    const float* __restrict__ src, long total,
    __nv_bfloat16* __restrict__ hi, __nv_bfloat16* __restrict__ lo)
{
    long i = (long)blockIdx.x * blockDim.x + threadIdx.x;
    if (i >= total) return;
    __nv_bfloat16 h, l; split_bf16(src[i], h, l);
    hi[i] = h; lo[i] = l;
}

// fused cvt for x_proj_w, dt_proj_w, out_proj_w (all contiguous)
#define C1 ((long)NXD * DIM)            // 196608
#define C2 (C1 + (long)DIM * DTRK)      // +131072
#define C3 (C2 + (long)DD * DIM)        // +2097152
__global__ __launch_bounds__(256) void cvt_rest_kernel(
    const float* __restrict__ s0, const float* __restrict__ s1,
    const float* __restrict__ s2,
    __nv_bfloat16* __restrict__ h0, __nv_bfloat16* __restrict__ l0,
    __nv_bfloat16* __restrict__ h1, __nv_bfloat16* __restrict__ l1,
    __nv_bfloat16* __restrict__ h2, __nv_bfloat16* __restrict__ l2)
{
    long i = (long)blockIdx.x * blockDim.x + threadIdx.x;
    if (i >= C3) return;
    const float* s; __nv_bfloat16 *ph, *pl; long j;
    if (i < C1)      { s = s0; ph = h0; pl = l0; j = i; }
    else if (i < C2) { s = s1; ph = h1; pl = l1; j = i - C1; }
    else             { s = s2; ph = h2; pl = l2; j = i - C2; }
    __nv_bfloat16 h, l; split_bf16(s[j], h, l);
    ph[j] = h; pl[j] = l;
}

// ---------------- fused add + LayerNorm (emits residual + h hi/lo) ----------
__global__ __launch_bounds__(256) void addnorm_kernel(
    const float* __restrict__ x, const float* __restrict__ res,
    const float* __restrict__ w, const float* __restrict__ b,
    float* __restrict__ res_out,
    __nv_bfloat16* __restrict__ h_hi, __nv_bfloat16* __restrict__ h_lo)
{
    const int row = blockIdx.x;
    const int tid = threadIdx.x;
    const float4* xv = reinterpret_cast<const float4*>(x + (size_t)row * DD);
    const float4* rv = reinterpret_cast<const float4*>(res + (size_t)row * DD);
    float4 a = xv[tid], r = rv[tid];
    float4 v = make_float4(a.x + r.x, a.y + r.y, a.z + r.z, a.w + r.w);
    reinterpret_cast<float4*>(res_out + (size_t)row * DD)[tid] = v;

    float s  = v.x + v.y + v.z + v.w;
    float ss = v.x*v.x + v.y*v.y + v.z*v.z + v.w*v.w;
    __shared__ float red[16];
    #pragma unroll
    for (int o = 16; o > 0; o >>= 1) {
        s  += __shfl_xor_sync(0xFFFFFFFFu, s,  o);
        ss += __shfl_xor_sync(0xFFFFFFFFu, ss, o);
    }
    int wid = tid >> 5, lane = tid & 31;
    if (lane == 0) { red[wid] = s; red[8 + wid] = ss; }
    __syncthreads();
    if (tid == 0) {
        float ts = 0.f, tss = 0.f;
        #pragma unroll
        for (int i = 0; i < 8; i++) { ts += red[i]; tss += red[8 + i]; }
        float mean = ts * (1.f / DD);
        float var  = tss * (1.f / DD) - mean * mean;
        red[0] = mean; red[1] = rsqrtf(var + 1e-5f);
    }
    __syncthreads();
    float mean = red[0], rstd = red[1];
    float4 wv = reinterpret_cast<const float4*>(w)[tid];
    float4 bv = reinterpret_cast<const float4*>(b)[tid];
    float hv[4];
    hv[0] = (v.x - mean) * rstd * wv.x + bv.x;
    hv[1] = (v.y - mean) * rstd * wv.y + bv.y;
    hv[2] = (v.z - mean) * rstd * wv.z + bv.z;
    hv[3] = (v.w - mean) * rstd * wv.w + bv.w;
    __nv_bfloat16 hh[4], ll[4];
    #pragma unroll
    for (int i = 0; i < 4; i++) split_bf16(hv[i], hh[i], ll[i]);
    size_t o = (size_t)row * DD + tid * 4;
    *reinterpret_cast<uint2*>(h_hi + o) = *reinterpret_cast<uint2*>(hh);
    *reinterpret_cast<uint2*>(h_lo + o) = *reinterpret_cast<uint2*>(ll);
}

// ---------------- causal depthwise conv (DC=4) + SiLU ------------------------
__global__ __launch_bounds__(256) void conv_silu_kernel(
    const float* __restrict__ xz, const float* __restrict__ cw,
    const float* __restrict__ cb, float* __restrict__ xc,
    __nv_bfloat16* __restrict__ xc_hi, __nv_bfloat16* __restrict__ xc_lo)
{
    int idx = blockIdx.x * blockDim.x + threadIdx.x;
    if (idx >= BB * LL * DIM) return;
    int d = idx % DIM;
    int t = (idx / DIM) % LL;
    int b = idx / (DIM * LL);
    float w0 = cw[d * 4 + 0], w1 = cw[d * 4 + 1];
    float w2 = cw[d * 4 + 2], w3 = cw[d * 4 + 3];
    size_t base = ((size_t)(b * LL + t)) * (2 * DIM) + d;
    float acc = cb[d];
    if (t >= 3) acc = fmaf(xz[base - 3 * (size_t)(2 * DIM)], w0, acc);
    if (t >= 2) acc = fmaf(xz[base - 2 * (size_t)(2 * DIM)], w1, acc);
    if (t >= 1) acc = fmaf(xz[base - 1 * (size_t)(2 * DIM)], w2, acc);
    acc = fmaf(xz[base], w3, acc);
    float sg = 1.f / (1.f + __expf(-acc));
    float v = acc * sg;
    xc[idx] = v;
    __nv_bfloat16 h, l; split_bf16(v, h, l);
    xc_hi[idx] = h; xc_lo[idx] = l;
}

// ---------------- selective scan (fused softplus, D-skip, SiLU gate) ---------
#define CH 32
__global__ __launch_bounds__(128) void scan_kernel(
    const float* __restrict__ xdbl, const float* __restrict__ dtraw,
    const float* __restrict__ dtb, const float* __restrict__ xc,
    const float* __restrict__ xz, const float* __restrict__ A_log,
    const float* __restrict__ Dp,
    __nv_bfloat16* __restrict__ y_hi, __nv_bfloat16* __restrict__ y_lo)
{
    const int b = blockIdx.y;
    const int d = blockIdx.x * 128 + threadIdx.x;
    float a[DS], h[DS];
    #pragma unroll
    for (int s = 0; s < DS; s++) {
        a[s] = -__expf(A_log[(size_t)d * DS + s]);
        h[s] = 0.f;
    }
    const float Dd   = Dp[d];
    const float bias = dtb[d];

    __shared__ float sB[CH][DS];
    __shared__ float sC[CH][DS];

    for (int t0 = 0; t0 < LL; t0 += CH) {
        __syncthreads();
        for (int idx = threadIdx.x; idx < CH * 32; idx += 128) {
            int r = idx >> 5, c = idx & 31;
            float v = xdbl[(size_t)(b * LL + t0 + r) * NXD + DTRK + c];
            if (c < DS) sB[r][c] = v; else sC[r][c - DS] = v;
        }
        __syncthreads();

        #pragma unroll 4
        for (int r = 0; r < CH; r++) {
            int t = t0 + r;
            size_t off = (size_t)(b * LL + t) * DIM + d;
            float dtv = dtraw[off] + bias;
            dtv = (dtv > 20.f) ? dtv : log1pf(__expf(dtv));
            float x = xc[off];
            float z = xz[(size_t)(b * LL + t) * (2 * DIM) + DIM + d];
            float dtx = dtv * x;
            float y = 0.f;
            #pragma unroll
            for (int s = 0; s < DS; s++) {
                float dA = __expf(dtv * a[s]);
                h[s] = fmaf(dA, h[s], dtx * sB[r][s]);
                y = fmaf(h[s], sC[r][s], y);
            }
            float sz = z / (1.f + __expf(-z));
            float yo = (y + Dd * x) * sz;
            __nv_bfloat16 hh, ll; split_bf16(yo, hh, ll);
            y_hi[off] = hh; y_lo[off] = ll;
        }
    }
}

// ---------------- launch ------------------------------------------------------
extern "C" void kernel_launch(void* const* d_in, const int* in_sizes, int n_in,
                              void* d_out, int out_size)
{
    const float* x          = (const float*)d_in[0];
    const float* residual   = (const float*)d_in[1];
    const float* ln_w       = (const float*)d_in[2];
    const float* ln_b       = (const float*)d_in[3];
    const float* in_proj_w  = (const float*)d_in[4];
    const float* conv_w     = (const float*)d_in[5];
    const float* conv_b     = (const float*)d_in[6];
    const float* x_proj_w   = (const float*)d_in[7];
    const float* dt_proj_w  = (const float*)d_in[8];
    const float* dt_proj_b  = (const float*)d_in[9];
    const float* A_log      = (const float*)d_in[10];
    const float* D_param    = (const float*)d_in[11];
    const float* out_proj_w = (const float*)d_in[12];

    float* out     = (float*)d_out;
    float* res_out = out + (size_t)BL * DD;

    float *xz, *xc, *xdbl, *dtraw;
    __nv_bfloat16 *h_hi, *h_lo, *wi_hi, *wi_lo, *xc_hi, *xc_lo, *xp_hi, *xp_lo;
    __nv_bfloat16 *dta_hi, *dta_lo, *dtw_hi, *dtw_lo, *y_hi, *y_lo, *ow_hi, *ow_lo;
    cudaGetSymbolAddress((void**)&xz,    g_xz);
    cudaGetSymbolAddress((void**)&xc,    g_xc);
    cudaGetSymbolAddress((void**)&xdbl,  g_xdbl);
    cudaGetSymbolAddress((void**)&dtraw, g_dtraw);
    cudaGetSymbolAddress((void**)&h_hi,  g_h_hi);  cudaGetSymbolAddress((void**)&h_lo,  g_h_lo);
    cudaGetSymbolAddress((void**)&wi_hi, g_wi_hi); cudaGetSymbolAddress((void**)&wi_lo, g_wi_lo);
    cudaGetSymbolAddress((void**)&xc_hi, g_xc_hi); cudaGetSymbolAddress((void**)&xc_lo, g_xc_lo);
    cudaGetSymbolAddress((void**)&xp_hi, g_xp_hi); cudaGetSymbolAddress((void**)&xp_lo, g_xp_lo);
    cudaGetSymbolAddress((void**)&dta_hi,g_dta_hi);cudaGetSymbolAddress((void**)&dta_lo,g_dta_lo);
    cudaGetSymbolAddress((void**)&dtw_hi,g_dtw_hi);cudaGetSymbolAddress((void**)&dtw_lo,g_dtw_lo);
    cudaGetSymbolAddress((void**)&y_hi,  g_y_hi);  cudaGetSymbolAddress((void**)&y_lo,  g_y_lo);
    cudaGetSymbolAddress((void**)&ow_hi, g_ow_hi); cudaGetSymbolAddress((void**)&ow_lo, g_ow_lo);

    cudaFuncSetAttribute(tc_gemm, cudaFuncAttributeMaxDynamicSharedMemorySize, GSMEM);

    // 0) in_proj weight cvt
    {
        long t1 = (long)2 * DIM * DD;
        cvt_flat_kernel<<<(int)((t1 + 255) / 256), 256>>>(in_proj_w, t1, wi_hi, wi_lo);
    }
    // 1) remaining weights (fused)
    cvt_rest_kernel<<<(int)((C3 + 255) / 256), 256>>>(
        x_proj_w, dt_proj_w, out_proj_w,
        xp_hi, xp_lo, dtw_hi, dtw_lo, ow_hi, ow_lo);

    // 2) residual = x + residual; h = LN(residual) -> hi/lo
    addnorm_kernel<<<BL, 256>>>(x, residual, ln_w, ln_b, res_out, h_hi, h_lo);

    // 3) xz = h @ in_proj_w^T   (M=4096, N=4096, K=1024)   <-- ncu window
    tc_gemm<<<dim3(2 * DIM / 128, BL / 128), 256, GSMEM>>>(
        h_hi, h_lo, wi_hi, wi_lo, xz, 2 * DIM, 2 * DIM, DD,
        ((__nv_bfloat16*)0), ((__nv_bfloat16*)0), 0);

    // 4) xc = silu(causal_conv(x_in))
    conv_silu_kernel<<<(BB * LL * DIM + 255) / 256, 256>>>(xz, conv_w, conv_b, xc, xc_hi, xc_lo);

    // 5) x_dbl = xc @ x_proj_w^T (M=4096, N=96, K=2048) + fused dt-slice cvt
    tc_gemm<<<dim3(1, BL / 128), 256, GSMEM>>>(
        xc_hi, xc_lo, xp_hi, xp_lo, xdbl, NXD, NXD, DIM,
        dta_hi, dta_lo, DTRK);

    // 6) dt_raw = dt_r @ dt_proj_w^T   (M=4096, N=2048, K=64)
    tc_gemm<<<dim3(DIM / 128, BL / 128), 256, GSMEM>>>(
        dta_hi, dta_lo, dtw_hi, dtw_lo, dtraw, DIM, DIM, DTRK,
        ((__nv_bfloat16*)0), ((__nv_bfloat16*)0), 0);

    // 7) selective scan -> y hi/lo
    scan_kernel<<<dim3(DIM / 128, BB), 128>>>(
        xdbl, dtraw, dt_proj_b, xc, xz, A_log, D_param, y_hi, y_lo);

    // 8) out = y @ out_proj_w^T   (M=4096, N=1024, K=2048)
    tc_gemm<<<dim3(DD / 128, BL / 128), 256, GSMEM>>>(
        y_hi, y_lo, ow_hi, ow_lo, out, DD, DD, DIM,
        ((__nv_bfloat16*)0), ((__nv_bfloat16*)0), 0);
}

// round 7
// speedup vs baseline: 3.6928x; 2.6611x over previous
#include <cuda_runtime.h>
#include <cuda_bf16.h>
#include <cstdint>
#include <math.h>

// Problem constants
#define BB   2
#define LL   2048
#define DD   1024
#define DIM  2048      // d_inner
#define DS   16        // d_state
#define DTRK 64        // dt_rank
#define NXD  96        // DTR + 2*DS
#define BL   (BB*LL)   // 4096 rows
#define NC   16        // scan chunks
#define CS   (LL/NC)   // 128 steps per chunk

// ---------------- scratch (device globals; no runtime allocation) ----------
__device__ __align__(256) float g_xz[(size_t)BL * 2 * DIM];
__device__ __align__(256) float g_xc[(size_t)BL * DIM];
__device__ __align__(256) float g_xdbl[(size_t)BL * NXD];
__device__ __align__(256) float g_dtraw[(size_t)BL * DIM];
__device__ __align__(256) float g_hend[(size_t)BB * NC * DS * DIM];
__device__ __align__(256) float g_P[(size_t)BB * NC * DS * DIM];
__device__ __align__(256) float g_h0[(size_t)BB * NC * DS * DIM];

__device__ __align__(256) __nv_bfloat16 g_h_hi[(size_t)BL * DD],    g_h_lo[(size_t)BL * DD];
__device__ __align__(256) __nv_bfloat16 g_wi_hi[(size_t)2*DIM*DD],  g_wi_lo[(size_t)2*DIM*DD];
__device__ __align__(256) __nv_bfloat16 g_xc_hi[(size_t)BL * DIM],  g_xc_lo[(size_t)BL * DIM];
__device__ __align__(256) __nv_bfloat16 g_xp_hi[(size_t)NXD * DIM], g_xp_lo[(size_t)NXD * DIM];
__device__ __align__(256) __nv_bfloat16 g_dta_hi[(size_t)BL * DTRK],g_dta_lo[(size_t)BL * DTRK];
__device__ __align__(256) __nv_bfloat16 g_dtw_hi[(size_t)DIM*DTRK], g_dtw_lo[(size_t)DIM*DTRK];
__device__ __align__(256) __nv_bfloat16 g_y_hi[(size_t)BL * DIM],   g_y_lo[(size_t)BL * DIM];
__device__ __align__(256) __nv_bfloat16 g_ow_hi[(size_t)DD * DIM],  g_ow_lo[(size_t)DD * DIM];

// ---------------- helpers ----------------------------------------------------
__device__ __forceinline__ uint32_t smem_u32(const void* p) {
    uint32_t a;
    asm("{ .reg .u64 t; cvta.to.shared.u64 t, %1; cvt.u32.u64 %0, t; }"
        : "=r"(a) : "l"(p));
    return a;
}
__device__ __forceinline__ void split_bf16(float v, __nv_bfloat16& hi, __nv_bfloat16& lo) {
    hi = __float2bfloat16(v);
    lo = __float2bfloat16(v - __bfloat162float(hi));
}
__device__ __forceinline__ float softplus_f(float x) {
    return (x > 20.f) ? x : log1pf(__expf(x));
}

__device__ __forceinline__ void ldm_x4(uint32_t addr, uint32_t r[4]) {
    asm volatile("ldmatrix.sync.aligned.m8n8.x4.shared.b16 {%0,%1,%2,%3}, [%4];"
        : "=r"(r[0]), "=r"(r[1]), "=r"(r[2]), "=r"(r[3]) : "r"(addr));
}
__device__ __forceinline__ void mma_bf16(float d[4], const uint32_t a[4],
                                         uint32_t b0, uint32_t b1) {
    asm volatile(
        "mma.sync.aligned.m16n8k16.row.col.f32.bf16.bf16.f32 "
        "{%0,%1,%2,%3}, {%4,%5,%6,%7}, {%8,%9}, {%0,%1,%2,%3};"
        : "+f"(d[0]), "+f"(d[1]), "+f"(d[2]), "+f"(d[3])
        : "r"(a[0]), "r"(a[1]), "r"(a[2]), "r"(a[3]), "r"(b0), "r"(b1));
}
__device__ __forceinline__ void cp16(uint32_t dst, const void* src, int srcsize) {
    asm volatile("cp.async.cg.shared.global [%0], [%1], 16, %2;"
                 :: "r"(dst), "l"(src), "r"(srcsize));
}
__device__ __forceinline__ void cp_commit() {
    asm volatile("cp.async.commit_group;");
}
__device__ __forceinline__ void cp_wait1() {
    asm volatile("cp.async.wait_group 1;");
}

// ---------------- split-bf16 tensor-core GEMM (mma.sync path) ----------------
#define SKB   80
#define TILEB (128 * SKB)
#define STAGEB (4 * TILEB)
#define GSMEM (2 * STAGEB)        // 81920 B dynamic smem

__global__ __launch_bounds__(256, 2) void tc_gemm(
    const __nv_bfloat16* __restrict__ Ahi, const __nv_bfloat16* __restrict__ Alo,
    const __nv_bfloat16* __restrict__ Bhi, const __nv_bfloat16* __restrict__ Blo,
    float* __restrict__ C, int ldc, int N, int K,
    __nv_bfloat16* __restrict__ Ehi, __nv_bfloat16* __restrict__ Elo, int ecols)
{
    extern __shared__ char smem[];
    const uint32_t sbase = smem_u32(smem);
    const int tid  = threadIdx.x;
    const int wid  = tid >> 5;
    const int lane = tid & 31;
    const int warp_m = wid & 3;
    const int warp_n = wid >> 2;
    const int m0 = blockIdx.y * 128;
    const int n0 = blockIdx.x * 128;

    const __nv_bfloat16* srcA[2] = { Ahi + (size_t)m0 * K, Alo + (size_t)m0 * K };
    const __nv_bfloat16* srcB[2] = { Bhi + (size_t)n0 * K, Blo + (size_t)n0 * K };

    float acc[2][8][4];
    #pragma unroll
    for (int a = 0; a < 2; a++)
        #pragma unroll
        for (int b = 0; b < 8; b++)
            #pragma unroll
            for (int c = 0; c < 4; c++) acc[a][b][c] = 0.f;

    const int nch = K / 32;

    auto load_chunk = [&](int stage, int k0) {
        const uint32_t base = sbase + stage * STAGEB;
        #pragma unroll
        for (int i = 0; i < 8; i++) {
            const int tile = i >> 1;
            const int rem  = ((i & 1) << 8) + tid;
            const int row  = rem >> 2;
            const int c    = rem & 3;
            const uint32_t dst = base + tile * TILEB + row * SKB + c * 16;
            const __nv_bfloat16* g;
            int sz = 16;
            if (tile < 2) {
                g = srcA[tile] + (size_t)row * K + k0 + c * 8;
            } else {
                g = srcB[tile - 2] + (size_t)row * K + k0 + c * 8;
                if (n0 + row >= N) sz = 0;
            }
            cp16(dst, g, sz);
        }
    };

    load_chunk(0, 0);
    cp_commit();

    for (int ch = 0; ch < nch; ch++) {
        if (ch + 1 < nch) load_chunk((ch + 1) & 1, (ch + 1) * 32);
        cp_commit();
        cp_wait1();
        __syncthreads();

        const uint32_t st = sbase + (ch & 1) * STAGEB;
        const uint32_t aHiB = st;
        const uint32_t aLoB = st + TILEB;
        const uint32_t bHiB = st + 2 * TILEB;
        const uint32_t bLoB = st + 3 * TILEB;

        #pragma unroll
        for (int k16 = 0; k16 < 2; k16++) {
            const int kcol = k16 * 16 + (lane >> 4) * 8;
            uint32_t ah[2][4], al[2][4], bh[4][4], bl[4][4];
            #pragma unroll
            for (int mf = 0; mf < 2; mf++) {
                const int row = warp_m * 32 + mf * 16 + (lane & 15);
                const uint32_t off = row * SKB + kcol * 2;
                ldm_x4(aHiB + off, ah[mf]);
                ldm_x4(aLoB + off, al[mf]);
            }
            #pragma unroll
            for (int nb = 0; nb < 4; nb++) {
                const int rowb = warp_n * 64 + nb * 16 + (lane & 15);
                const uint32_t offb = rowb * SKB + kcol * 2;
                ldm_x4(bHiB + offb, bh[nb]);
                ldm_x4(bLoB + offb, bl[nb]);
            }
            #pragma unroll
            for (int mf = 0; mf < 2; mf++)
                #pragma unroll
                for (int nb = 0; nb < 4; nb++) {
                    mma_bf16(acc[mf][nb*2],   ah[mf], bh[nb][0], bh[nb][2]);
                    mma_bf16(acc[mf][nb*2+1], ah[mf], bh[nb][1], bh[nb][3]);
                }
            #pragma unroll
            for (int mf = 0; mf < 2; mf++)
                #pragma unroll
                for (int nb = 0; nb < 4; nb++) {
                    mma_bf16(acc[mf][nb*2],   ah[mf], bl[nb][0], bl[nb][2]);
                    mma_bf16(acc[mf][nb*2+1], ah[mf], bl[nb][1], bl[nb][3]);
                }
            #pragma unroll
            for (int mf = 0; mf < 2; mf++)
                #pragma unroll
                for (int nb = 0; nb < 4; nb++) {
                    mma_bf16(acc[mf][nb*2],   al[mf], bh[nb][0], bh[nb][2]);
                    mma_bf16(acc[mf][nb*2+1], al[mf], bh[nb][1], bh[nb][3]);
                }
        }
        __syncthreads();
    }

    #pragma unroll
    for (int mf = 0; mf < 2; mf++) {
        #pragma unroll
        for (int nf = 0; nf < 8; nf++) {
            const int r0  = m0 + warp_m * 32 + mf * 16 + (lane >> 2);
            const int col = n0 + warp_n * 64 + nf * 8 + (lane & 3) * 2;
            if (col < N) {
                float2 v0 = make_float2(acc[mf][nf][0], acc[mf][nf][1]);
                float2 v1 = make_float2(acc[mf][nf][2], acc[mf][nf][3]);
                *reinterpret_cast<float2*>(C + (size_t)r0 * ldc + col) = v0;
                *reinterpret_cast<float2*>(C + (size_t)(r0 + 8) * ldc + col) = v1;
                if (Ehi && col < ecols) {
                    __nv_bfloat16 h0, l0, h1, l1;
                    split_bf16(v0.x, h0, l0); split_bf16(v0.y, h1, l1);
                    __nv_bfloat162 hh = __nv_bfloat162(h0, h1);
                    __nv_bfloat162 ll = __nv_bfloat162(l0, l1);
                    *reinterpret_cast<__nv_bfloat162*>(Ehi + (size_t)r0 * ecols + col) = hh;
                    *reinterpret_cast<__nv_bfloat162*>(Elo + (size_t)r0 * ecols + col) = ll;
                    split_bf16(v1.x, h0, l0); split_bf16(v1.y, h1, l1);
                    hh = __nv_bfloat162(h0, h1); ll = __nv_bfloat162(l0, l1);
                    *reinterpret_cast<__nv_bfloat162*>(Ehi + (size_t)(r0+8) * ecols + col) = hh;
                    *reinterpret_cast<__nv_bfloat162*>(Elo + (size_t)(r0+8) * ecols + col) = ll;
                }
            }
        }
    }
}

// ---------------- weight conversions ----------------------------------------
__global__ __launch_bounds__(256) void cvt_flat_kernel(
    const float* __restrict__ src, long total,
    __nv_bfloat16* __restrict__ hi, __nv_bfloat16* __restrict__ lo)
{
    long i = (long)blockIdx.x * blockDim.x + threadIdx.x;
    if (i >= total) return;
    __nv_bfloat16 h, l; split_bf16(src[i], h, l);
    hi[i] = h; lo[i] = l;
}

#define C1 ((long)NXD * DIM)
#define C2 (C1 + (long)DIM * DTRK)
#define C3 (C2 + (long)DD * DIM)
__global__ __launch_bounds__(256) void cvt_rest_kernel(
    const float* __restrict__ s0, const float* __restrict__ s1,
    const float* __restrict__ s2,
    __nv_bfloat16* __restrict__ h0, __nv_bfloat16* __restrict__ l0,
    __nv_bfloat16* __restrict__ h1, __nv_bfloat16* __restrict__ l1,
    __nv_bfloat16* __restrict__ h2, __nv_bfloat16* __restrict__ l2)
{
    long i = (long)blockIdx.x * blockDim.x + threadIdx.x;
    if (i >= C3) return;
    const float* s; __nv_bfloat16 *ph, *pl; long j;
    if (i < C1)      { s = s0; ph = h0; pl = l0; j = i; }
    else if (i < C2) { s = s1; ph = h1; pl = l1; j = i - C1; }
    else             { s = s2; ph = h2; pl = l2; j = i - C2; }
    __nv_bfloat16 h, l; split_bf16(s[j], h, l);
    ph[j] = h; pl[j] = l;
}

// ---------------- fused add + LayerNorm (emits residual + h hi/lo) ----------
__global__ __launch_bounds__(256) void addnorm_kernel(
    const float* __restrict__ x, const float* __restrict__ res,
    const float* __restrict__ w, const float* __restrict__ b,
    float* __restrict__ res_out,
    __nv_bfloat16* __restrict__ h_hi, __nv_bfloat16* __restrict__ h_lo)
{
    const int row = blockIdx.x;
    const int tid = threadIdx.x;
    const float4* xv = reinterpret_cast<const float4*>(x + (size_t)row * DD);
    const float4* rv = reinterpret_cast<const float4*>(res + (size_t)row * DD);
    float4 a = xv[tid], r = rv[tid];
    float4 v = make_float4(a.x + r.x, a.y + r.y, a.z + r.z, a.w + r.w);
    reinterpret_cast<float4*>(res_out + (size_t)row * DD)[tid] = v;

    float s  = v.x + v.y + v.z + v.w;
    float ss = v.x*v.x + v.y*v.y + v.z*v.z + v.w*v.w;
    __shared__ float red[16];
    #pragma unroll
    for (int o = 16; o > 0; o >>= 1) {
        s  += __shfl_xor_sync(0xFFFFFFFFu, s,  o);
        ss += __shfl_xor_sync(0xFFFFFFFFu, ss, o);
    }
    int wid = tid >> 5, lane = tid & 31;
    if (lane == 0) { red[wid] = s; red[8 + wid] = ss; }
    __syncthreads();
    if (tid == 0) {
        float ts = 0.f, tss = 0.f;
        #pragma unroll
        for (int i = 0; i < 8; i++) { ts += red[i]; tss += red[8 + i]; }
        float mean = ts * (1.f / DD);
        float var  = tss * (1.f / DD) - mean * mean;
        red[0] = mean; red[1] = rsqrtf(var + 1e-5f);
    }
    __syncthreads();
    float mean = red[0], rstd = red[1];
    float4 wv = reinterpret_cast<const float4*>(w)[tid];
    float4 bv = reinterpret_cast<const float4*>(b)[tid];
    float hv[4];
    hv[0] = (v.x - mean) * rstd * wv.x + bv.x;
    hv[1] = (v.y - mean) * rstd * wv.y + bv.y;
    hv[2] = (v.z - mean) * rstd * wv.z + bv.z;
    hv[3] = (v.w - mean) * rstd * wv.w + bv.w;
    __nv_bfloat16 hh[4], ll[4];
    #pragma unroll
    for (int i = 0; i < 4; i++) split_bf16(hv[i], hh[i], ll[i]);
    size_t o = (size_t)row * DD + tid * 4;
    *reinterpret_cast<uint2*>(h_hi + o) = *reinterpret_cast<uint2*>(hh);
    *reinterpret_cast<uint2*>(h_lo + o) = *reinterpret_cast<uint2*>(ll);
}

// ---------------- causal depthwise conv (DC=4) + SiLU ------------------------
__global__ __launch_bounds__(256) void conv_silu_kernel(
    const float* __restrict__ xz, const float* __restrict__ cw,
    const float* __restrict__ cb, float* __restrict__ xc,
    __nv_bfloat16* __restrict__ xc_hi, __nv_bfloat16* __restrict__ xc_lo)
{
    int idx = blockIdx.x * blockDim.x + threadIdx.x;
    if (idx >= BB * LL * DIM) return;
    int d = idx % DIM;
    int t = (idx / DIM) % LL;
    int b = idx / (DIM * LL);
    float w0 = cw[d * 4 + 0], w1 = cw[d * 4 + 1];
    float w2 = cw[d * 4 + 2], w3 = cw[d * 4 + 3];
    size_t base = ((size_t)(b * LL + t)) * (2 * DIM) + d;
    float acc = cb[d];
    if (t >= 3) acc = fmaf(xz[base - 3 * (size_t)(2 * DIM)], w0, acc);
    if (t >= 2) acc = fmaf(xz[base - 2 * (size_t)(2 * DIM)], w1, acc);
    if (t >= 1) acc = fmaf(xz[base - 1 * (size_t)(2 * DIM)], w2, acc);
    acc = fmaf(xz[base], w3, acc);
    float sg = 1.f / (1.f + __expf(-acc));
    float v = acc * sg;
    xc[idx] = v;
    __nv_bfloat16 h, l; split_bf16(v, h, l);
    xc_hi[idx] = h; xc_lo[idx] = l;
}

// ---------------- chunked selective scan --------------------------------------
// pass1: per-chunk local scan from h=0 -> hend[s], P[s]=exp(a[s]*sum_dt)
// pass2: serial combine over NC chunks -> h0 per chunk
// pass3: per-chunk scan from h0, fused D-skip + SiLU(z) gate -> y hi/lo
#define CH 32

__global__ __launch_bounds__(128) void scan_pass1(
    const float* __restrict__ xdbl, const float* __restrict__ dtraw,
    const float* __restrict__ dtb, const float* __restrict__ xc,
    const float* __restrict__ A_log,
    float* __restrict__ hend, float* __restrict__ Pbuf)
{
    const int b = blockIdx.z, c = blockIdx.y;
    const int d = blockIdx.x * 128 + threadIdx.x;
    float a[DS], h[DS];
    #pragma unroll
    for (int s = 0; s < DS; s++) {
        a[s] = -__expf(A_log[(size_t)d * DS + s]);
        h[s] = 0.f;
    }
    const float bias = dtb[d];
    float sumdt = 0.f;
    __shared__ float sB[CH][DS];
    const int tbase = c * CS;

    for (int t0 = 0; t0 < CS; t0 += CH) {
        __syncthreads();
        for (int idx = threadIdx.x; idx < CH * DS; idx += 128) {
            int r = idx >> 4, col = idx & 15;
            sB[r][col] = xdbl[(size_t)(b * LL + tbase + t0 + r) * NXD + DTRK + col];
        }
        __syncthreads();
        #pragma unroll 4
        for (int r = 0; r < CH; r++) {
            size_t off = (size_t)(b * LL + tbase + t0 + r) * DIM + d;
            float dtv = softplus_f(dtraw[off] + bias);
            sumdt += dtv;
            float dtx = dtv * xc[off];
            #pragma unroll
            for (int s = 0; s < DS; s++)
                h[s] = fmaf(__expf(dtv * a[s]), h[s], dtx * sB[r][s]);
        }
    }
    size_t obase = ((size_t)(b * NC + c) * DS) * DIM + d;
    #pragma unroll
    for (int s = 0; s < DS; s++) {
        hend[obase + (size_t)s * DIM] = h[s];
        Pbuf[obase + (size_t)s * DIM] = __expf(a[s] * sumdt);
    }
}

__global__ __launch_bounds__(128) void scan_pass2(
    const float* __restrict__ hend, const float* __restrict__ Pbuf,
    float* __restrict__ h0buf)
{
    const int b = blockIdx.y;
    const int d = blockIdx.x * 128 + threadIdx.x;
    float h0[DS];
    #pragma unroll
    for (int s = 0; s < DS; s++) h0[s] = 0.f;
    for (int c = 0; c < NC; c++) {
        size_t base = ((size_t)(b * NC + c) * DS) * DIM + d;
        #pragma unroll
        for (int s = 0; s < DS; s++) {
            h0buf[base + (size_t)s * DIM] = h0[s];
            h0[s] = fmaf(Pbuf[base + (size_t)s * DIM], h0[s],
                         hend[base + (size_t)s * DIM]);
        }
    }
}

__global__ __launch_bounds__(128) void scan_pass3(
    const float* __restrict__ xdbl, const float* __restrict__ dtraw,
    const float* __restrict__ dtb, const float* __restrict__ xc,
    const float* __restrict__ xz, const float* __restrict__ A_log,
    const float* __restrict__ Dp, const float* __restrict__ h0buf,
    __nv_bfloat16* __restrict__ y_hi, __nv_bfloat16* __restrict__ y_lo)
{
    const int b = blockIdx.z, c = blockIdx.y;
    const int d = blockIdx.x * 128 + threadIdx.x;
    float a[DS], h[DS];
    size_t hbase = ((size_t)(b * NC + c) * DS) * DIM + d;
    #pragma unroll
    for (int s = 0; s < DS; s++) {
        a[s] = -__expf(A_log[(size_t)d * DS + s]);
        h[s] = h0buf[hbase + (size_t)s * DIM];
    }
    const float Dd   = Dp[d];
    const float bias = dtb[d];
    __shared__ float sB[CH][DS];
    __shared__ float sC[CH][DS];
    const int tbase = c * CS;

    for (int t0 = 0; t0 < CS; t0 += CH) {
        __syncthreads();
        for (int idx = threadIdx.x; idx < CH * 32; idx += 128) {
            int r = idx >> 5, col = idx & 31;
            float v = xdbl[(size_t)(b * LL + tbase + t0 + r) * NXD + DTRK + col];
            if (col < DS) sB[r][col] = v; else sC[r][col - DS] = v;
        }
        __syncthreads();
        #pragma unroll 4
        for (int r = 0; r < CH; r++) {
            int t = tbase + t0 + r;
            size_t off = (size_t)(b * LL + t) * DIM + d;
            float dtv = softplus_f(dtraw[off] + bias);
            float x = xc[off];
            float z = xz[(size_t)(b * LL + t) * (2 * DIM) + DIM + d];
            float dtx = dtv * x;
            float y = 0.f;
            #pragma unroll
            for (int s = 0; s < DS; s++) {
                h[s] = fmaf(__expf(dtv * a[s]), h[s], dtx * sB[r][s]);
                y = fmaf(h[s], sC[r][s], y);
            }
            float sz = z / (1.f + __expf(-z));
            float yo = (y + Dd * x) * sz;
            __nv_bfloat16 hh, ll; split_bf16(yo, hh, ll);
            y_hi[off] = hh; y_lo[off] = ll;
        }
    }
}

// ---------------- launch ------------------------------------------------------
extern "C" void kernel_launch(void* const* d_in, const int* in_sizes, int n_in,
                              void* d_out, int out_size)
{
    const float* x          = (const float*)d_in[0];
    const float* residual   = (const float*)d_in[1];
    const float* ln_w       = (const float*)d_in[2];
    const float* ln_b       = (const float*)d_in[3];
    const float* in_proj_w  = (const float*)d_in[4];
    const float* conv_w     = (const float*)d_in[5];
    const float* conv_b     = (const float*)d_in[6];
    const float* x_proj_w   = (const float*)d_in[7];
    const float* dt_proj_w  = (const float*)d_in[8];
    const float* dt_proj_b  = (const float*)d_in[9];
    const float* A_log      = (const float*)d_in[10];
    const float* D_param    = (const float*)d_in[11];
    const float* out_proj_w = (const float*)d_in[12];

    float* out     = (float*)d_out;
    float* res_out = out + (size_t)BL * DD;

    float *xz, *xc, *xdbl, *dtraw, *hend, *Pbuf, *h0buf;
    __nv_bfloat16 *h_hi, *h_lo, *wi_hi, *wi_lo, *xc_hi, *xc_lo, *xp_hi, *xp_lo;
    __nv_bfloat16 *dta_hi, *dta_lo, *dtw_hi, *dtw_lo, *y_hi, *y_lo, *ow_hi, *ow_lo;
    cudaGetSymbolAddress((void**)&xz,    g_xz);
    cudaGetSymbolAddress((void**)&xc,    g_xc);
    cudaGetSymbolAddress((void**)&xdbl,  g_xdbl);
    cudaGetSymbolAddress((void**)&dtraw, g_dtraw);
    cudaGetSymbolAddress((void**)&hend,  g_hend);
    cudaGetSymbolAddress((void**)&Pbuf,  g_P);
    cudaGetSymbolAddress((void**)&h0buf, g_h0);
    cudaGetSymbolAddress((void**)&h_hi,  g_h_hi);  cudaGetSymbolAddress((void**)&h_lo,  g_h_lo);
    cudaGetSymbolAddress((void**)&wi_hi, g_wi_hi); cudaGetSymbolAddress((void**)&wi_lo, g_wi_lo);
    cudaGetSymbolAddress((void**)&xc_hi, g_xc_hi); cudaGetSymbolAddress((void**)&xc_lo, g_xc_lo);
    cudaGetSymbolAddress((void**)&xp_hi, g_xp_hi); cudaGetSymbolAddress((void**)&xp_lo, g_xp_lo);
    cudaGetSymbolAddress((void**)&dta_hi,g_dta_hi);cudaGetSymbolAddress((void**)&dta_lo,g_dta_lo);
    cudaGetSymbolAddress((void**)&dtw_hi,g_dtw_hi);cudaGetSymbolAddress((void**)&dtw_lo,g_dtw_lo);
    cudaGetSymbolAddress((void**)&y_hi,  g_y_hi);  cudaGetSymbolAddress((void**)&y_lo,  g_y_lo);
    cudaGetSymbolAddress((void**)&ow_hi, g_ow_hi); cudaGetSymbolAddress((void**)&ow_lo, g_ow_lo);

    cudaFuncSetAttribute(tc_gemm, cudaFuncAttributeMaxDynamicSharedMemorySize, GSMEM);

    // 0) in_proj weight cvt
    {
        long t1 = (long)2 * DIM * DD;
        cvt_flat_kernel<<<(int)((t1 + 255) / 256), 256>>>(in_proj_w, t1, wi_hi, wi_lo);
    }
    // 1) remaining weights (fused)
    cvt_rest_kernel<<<(int)((C3 + 255) / 256), 256>>>(
        x_proj_w, dt_proj_w, out_proj_w,
        xp_hi, xp_lo, dtw_hi, dtw_lo, ow_hi, ow_lo);

    // 2) residual = x + residual; h = LN(residual) -> hi/lo
    addnorm_kernel<<<BL, 256>>>(x, residual, ln_w, ln_b, res_out, h_hi, h_lo);

    // 3) xz = h @ in_proj_w^T   (M=4096, N=4096, K=1024)   <-- ncu window
    tc_gemm<<<dim3(2 * DIM / 128, BL / 128), 256, GSMEM>>>(
        h_hi, h_lo, wi_hi, wi_lo, xz, 2 * DIM, 2 * DIM, DD,
        ((__nv_bfloat16*)0), ((__nv_bfloat16*)0), 0);

    // 4) xc = silu(causal_conv(x_in))
    conv_silu_kernel<<<(BB * LL * DIM + 255) / 256, 256>>>(xz, conv_w, conv_b, xc, xc_hi, xc_lo);

    // 5) x_dbl = xc @ x_proj_w^T (M=4096, N=96, K=2048) + fused dt-slice cvt
    tc_gemm<<<dim3(1, BL / 128), 256, GSMEM>>>(
        xc_hi, xc_lo, xp_hi, xp_lo, xdbl, NXD, NXD, DIM,
        dta_hi, dta_lo, DTRK);

    // 6) dt_raw = dt_r @ dt_proj_w^T   (M=4096, N=2048, K=64)
    tc_gemm<<<dim3(DIM / 128, BL / 128), 256, GSMEM>>>(
        dta_hi, dta_lo, dtw_hi, dtw_lo, dtraw, DIM, DIM, DTRK,
        ((__nv_bfloat16*)0), ((__nv_bfloat16*)0), 0);

    // 7) chunked selective scan
    scan_pass1<<<dim3(DIM / 128, NC, BB), 128>>>(
        xdbl, dtraw, dt_proj_b, xc, A_log, hend, Pbuf);
    scan_pass2<<<dim3(DIM / 128, BB), 128>>>(hend, Pbuf, h0buf);
    scan_pass3<<<dim3(DIM / 128, NC, BB), 128>>>(
        xdbl, dtraw, dt_proj_b, xc, xz, A_log, D_param, h0buf, y_hi, y_lo);

    // 8) out = y @ out_proj_w^T   (M=4096, N=1024, K=2048)
    tc_gemm<<<dim3(DD / 128, BL / 128), 256, GSMEM>>>(
        y_hi, y_lo, ow_hi, ow_lo, out, DD, DD, DIM,
        ((__nv_bfloat16*)0), ((__nv_bfloat16*)0), 0);
}

// round 8
// speedup vs baseline: 4.3643x; 1.1819x over previous
#include <cuda_runtime.h>
#include <cuda_bf16.h>
#include <cstdint>
#include <math.h>

// Problem constants
#define BB   2
#define LL   2048
#define DD   1024
#define DIM  2048      // d_inner
#define DS   16        // d_state
#define DTRK 64        // dt_rank
#define NXD  96        // DTR + 2*DS
#define BL   (BB*LL)   // 4096 rows
#define NC   16        // scan chunks
#define CS   (LL/NC)   // 128 steps per chunk
#define KSPL 8         // x_proj split-K factor

// ---------------- scratch (device globals; no runtime allocation) ----------
__device__ __align__(256) float g_xz[(size_t)BL * 2 * DIM];
__device__ __align__(256) float g_xc[(size_t)BL * DIM];
__device__ __align__(256) float g_xdbl[(size_t)BL * NXD];
__device__ __align__(256) float g_xpart[(size_t)KSPL * BL * NXD];
__device__ __align__(256) float g_dtraw[(size_t)BL * DIM];
__device__ __align__(256) float g_hend[(size_t)BB * NC * DS * DIM];
__device__ __align__(256) float g_P[(size_t)BB * NC * DS * DIM];
__device__ __align__(256) float g_h0[(size_t)BB * NC * DS * DIM];

__device__ __align__(256) __nv_bfloat16 g_h_hi[(size_t)BL * DD],    g_h_lo[(size_t)BL * DD];
__device__ __align__(256) __nv_bfloat16 g_wi_hi[(size_t)2*DIM*DD],  g_wi_lo[(size_t)2*DIM*DD];
__device__ __align__(256) __nv_bfloat16 g_xc_hi[(size_t)BL * DIM],  g_xc_lo[(size_t)BL * DIM];
__device__ __align__(256) __nv_bfloat16 g_xp_hi[(size_t)NXD * DIM], g_xp_lo[(size_t)NXD * DIM];
__device__ __align__(256) __nv_bfloat16 g_dta_hi[(size_t)BL * DTRK],g_dta_lo[(size_t)BL * DTRK];
__device__ __align__(256) __nv_bfloat16 g_dtw_hi[(size_t)DIM*DTRK], g_dtw_lo[(size_t)DIM*DTRK];
__device__ __align__(256) __nv_bfloat16 g_y_hi[(size_t)BL * DIM],   g_y_lo[(size_t)BL * DIM];
__device__ __align__(256) __nv_bfloat16 g_ow_hi[(size_t)DD * DIM],  g_ow_lo[(size_t)DD * DIM];

// ---------------- helpers ----------------------------------------------------
__device__ __forceinline__ uint32_t smem_u32(const void* p) {
    uint32_t a;
    asm("{ .reg .u64 t; cvta.to.shared.u64 t, %1; cvt.u32.u64 %0, t; }"
        : "=r"(a) : "l"(p));
    return a;
}
__device__ __forceinline__ void split_bf16(float v, __nv_bfloat16& hi, __nv_bfloat16& lo) {
    hi = __float2bfloat16(v);
    lo = __float2bfloat16(v - __bfloat162float(hi));
}
__device__ __forceinline__ float softplus_f(float x) {
    return (x > 20.f) ? x : log1pf(__expf(x));
}

__device__ __forceinline__ void ldm_x4(uint32_t addr, uint32_t r[4]) {
    asm volatile("ldmatrix.sync.aligned.m8n8.x4.shared.b16 {%0,%1,%2,%3}, [%4];"
        : "=r"(r[0]), "=r"(r[1]), "=r"(r[2]), "=r"(r[3]) : "r"(addr));
}
__device__ __forceinline__ void mma_bf16(float d[4], const uint32_t a[4],
                                         uint32_t b0, uint32_t b1) {
    asm volatile(
        "mma.sync.aligned.m16n8k16.row.col.f32.bf16.bf16.f32 "
        "{%0,%1,%2,%3}, {%4,%5,%6,%7}, {%8,%9}, {%0,%1,%2,%3};"
        : "+f"(d[0]), "+f"(d[1]), "+f"(d[2]), "+f"(d[3])
        : "r"(a[0]), "r"(a[1]), "r"(a[2]), "r"(a[3]), "r"(b0), "r"(b1));
}
__device__ __forceinline__ void cp16(uint32_t dst, const void* src, int srcsize) {
    asm volatile("cp.async.cg.shared.global [%0], [%1], 16, %2;"
                 :: "r"(dst), "l"(src), "r"(srcsize));
}
__device__ __forceinline__ void cp_commit() {
    asm volatile("cp.async.commit_group;");
}
__device__ __forceinline__ void cp_wait2() {
    asm volatile("cp.async.wait_group 2;");
}

// ---------------- split-bf16 tensor-core GEMM (mma.sync path) ----------------
// C[m][n] = sum_k A[m][k]*B[n][k]; A,B as bf16 hi/lo pairs (K-contiguous, ld=ldK).
// 128x128 CTA tile, BK=32, 8 warps (4m x 2n). 3-stage cp.async pipeline.
// Smem: 64B rows with XOR swizzle (chunk ^= (row>>1)&3) -> conflict-free LDSM,
// 16B-aligned cp.async. Split-K via blockIdx.z (kbase = z*Ksub, C += z*cstride).
#define TILEB 8192                 // 128 rows * 64 B
#define STAGE3 (4 * TILEB)         // 32768 B per stage
#define GSMEM (3 * STAGE3)         // 98304 B dynamic smem

__global__ __launch_bounds__(256, 2) void tc_gemm(
    const __nv_bfloat16* __restrict__ Ahi, const __nv_bfloat16* __restrict__ Alo,
    const __nv_bfloat16* __restrict__ Bhi, const __nv_bfloat16* __restrict__ Blo,
    float* __restrict__ C, int ldc, int N, int ldK, int Ksub, long cstride,
    __nv_bfloat16* __restrict__ Ehi, __nv_bfloat16* __restrict__ Elo, int ecols)
{
    extern __shared__ char smem[];
    const uint32_t sbase = smem_u32(smem);
    const int tid  = threadIdx.x;
    const int wid  = tid >> 5;
    const int lane = tid & 31;
    const int warp_m = wid & 3;
    const int warp_n = wid >> 2;
    const int m0 = blockIdx.y * 128;
    const int n0 = blockIdx.x * 128;
    const int kbase = blockIdx.z * Ksub;
    C += (long)blockIdx.z * cstride;

    const __nv_bfloat16* srcA[2] = { Ahi + (size_t)m0 * ldK + kbase,
                                     Alo + (size_t)m0 * ldK + kbase };
    const __nv_bfloat16* srcB[2] = { Bhi + (size_t)n0 * ldK + kbase,
                                     Blo + (size_t)n0 * ldK + kbase };

    float acc[2][8][4];
    #pragma unroll
    for (int a = 0; a < 2; a++)
        #pragma unroll
        for (int b = 0; b < 8; b++)
            #pragma unroll
            for (int c = 0; c < 4; c++) acc[a][b][c] = 0.f;

    const int nch = Ksub / 32;

    auto load_chunk = [&](int stage, int k0) {
        const uint32_t base = sbase + stage * STAGE3;
        #pragma unroll
        for (int i = 0; i < 8; i++) {
            const int tile = i >> 1;
            const int rem  = ((i & 1) << 8) + tid;
            const int row  = rem >> 2;
            const int c    = rem & 3;
            const int csw  = c ^ ((row >> 1) & 3);
            const uint32_t dst = base + tile * TILEB + row * 64 + csw * 16;
            const __nv_bfloat16* g;
            int sz = 16;
            if (tile < 2) {
                g = srcA[tile] + (size_t)row * ldK + k0 + c * 8;
            } else {
                g = srcB[tile - 2] + (size_t)row * ldK + k0 + c * 8;
                if (n0 + row >= N) sz = 0;
            }
            cp16(dst, g, sz);
        }
    };

    load_chunk(0, 0);
    cp_commit();
    if (1 < nch) load_chunk(1, 32);
    cp_commit();

    for (int ch = 0; ch < nch; ch++) {
        if (ch + 2 < nch) load_chunk((ch + 2) % 3, (ch + 2) * 32);
        cp_commit();            // always commit (empty groups keep count aligned)
        cp_wait2();             // committed = ch+3; <=2 outstanding -> chunk ch done
        __syncthreads();

        const uint32_t st = sbase + (ch % 3) * STAGE3;
        const uint32_t aHiB = st;
        const uint32_t aLoB = st + TILEB;
        const uint32_t bHiB = st + 2 * TILEB;
        const uint32_t bLoB = st + 3 * TILEB;

        #pragma unroll
        for (int k16 = 0; k16 < 2; k16++) {
            uint32_t ah[2][4], al[2][4], bh[4][4], bl[4][4];
            const int ci = k16 * 2 + (lane >> 4);          // 16B chunk index 0..3
            #pragma unroll
            for (int mf = 0; mf < 2; mf++) {
                const int row = warp_m * 32 + mf * 16 + (lane & 15);
                const uint32_t off = row * 64 + ((ci ^ ((row >> 1) & 3)) * 16);
                ldm_x4(aHiB + off, ah[mf]);
                ldm_x4(aLoB + off, al[mf]);
            }
            #pragma unroll
            for (int nb = 0; nb < 4; nb++) {
                const int rowb = warp_n * 64 + nb * 16 + (lane & 15);
                const uint32_t offb = rowb * 64 + ((ci ^ ((rowb >> 1) & 3)) * 16);
                ldm_x4(bHiB + offb, bh[nb]);
                ldm_x4(bLoB + offb, bl[nb]);
            }
            #pragma unroll
            for (int mf = 0; mf < 2; mf++)
                #pragma unroll
                for (int nb = 0; nb < 4; nb++) {
                    mma_bf16(acc[mf][nb*2],   ah[mf], bh[nb][0], bh[nb][2]);
                    mma_bf16(acc[mf][nb*2+1], ah[mf], bh[nb][1], bh[nb][3]);
                }
            #pragma unroll
            for (int mf = 0; mf < 2; mf++)
                #pragma unroll
                for (int nb = 0; nb < 4; nb++) {
                    mma_bf16(acc[mf][nb*2],   ah[mf], bl[nb][0], bl[nb][2]);
                    mma_bf16(acc[mf][nb*2+1], ah[mf], bl[nb][1], bl[nb][3]);
                }
            #pragma unroll
            for (int mf = 0; mf < 2; mf++)
                #pragma unroll
                for (int nb = 0; nb < 4; nb++) {
                    mma_bf16(acc[mf][nb*2],   al[mf], bh[nb][0], bh[nb][2]);
                    mma_bf16(acc[mf][nb*2+1], al[mf], bh[nb][1], bh[nb][3]);
                }
        }
        __syncthreads();
    }

    #pragma unroll
    for (int mf = 0; mf < 2; mf++) {
        #pragma unroll
        for (int nf = 0; nf < 8; nf++) {
            const int r0  = m0 + warp_m * 32 + mf * 16 + (lane >> 2);
            const int col = n0 + warp_n * 64 + nf * 8 + (lane & 3) * 2;
            if (col < N) {
                float2 v0 = make_float2(acc[mf][nf][0], acc[mf][nf][1]);
                float2 v1 = make_float2(acc[mf][nf][2], acc[mf][nf][3]);
                *reinterpret_cast<float2*>(C + (size_t)r0 * ldc + col) = v0;
                *reinterpret_cast<float2*>(C + (size_t)(r0 + 8) * ldc + col) = v1;
                if (Ehi && col < ecols) {
                    __nv_bfloat16 h0, l0, h1, l1;
                    split_bf16(v0.x, h0, l0); split_bf16(v0.y, h1, l1);
                    __nv_bfloat162 hh = __nv_bfloat162(h0, h1);
                    __nv_bfloat162 ll = __nv_bfloat162(l0, l1);
                    *reinterpret_cast<__nv_bfloat162*>(Ehi + (size_t)r0 * ecols + col) = hh;
                    *reinterpret_cast<__nv_bfloat162*>(Elo + (size_t)r0 * ecols + col) = ll;
                    split_bf16(v1.x, h0, l0); split_bf16(v1.y, h1, l1);
                    hh = __nv_bfloat162(h0, h1); ll = __nv_bfloat162(l0, l1);
                    *reinterpret_cast<__nv_bfloat162*>(Ehi + (size_t)(r0+8) * ecols + col) = hh;
                    *reinterpret_cast<__nv_bfloat162*>(Elo + (size_t)(r0+8) * ecols + col) = ll;
                }
            }
        }
    }
}

// ---------------- split-K reduce for x_proj + fused dt-slice cvt -------------
__global__ __launch_bounds__(256) void xpart_reduce_kernel(
    const float* __restrict__ part, float* __restrict__ xdbl,
    __nv_bfloat16* __restrict__ dta_hi, __nv_bfloat16* __restrict__ dta_lo)
{
    int i = blockIdx.x * blockDim.x + threadIdx.x;      // over BL*NXD
    if (i >= BL * NXD) return;
    float s = 0.f;
    #pragma unroll
    for (int z = 0; z < KSPL; z++) s += part[(size_t)z * BL * NXD + i];
    xdbl[i] = s;
    int col = i % NXD;
    if (col < DTRK) {
        int row = i / NXD;
        __nv_bfloat16 h, l; split_bf16(s, h, l);
        dta_hi[(size_t)row * DTRK + col] = h;
        dta_lo[(size_t)row * DTRK + col] = l;
    }
}

// ---------------- weight conversions ----------------------------------------
__global__ __launch_bounds__(256) void cvt_flat_kernel(
    const float* __restrict__ src, long total,
    __nv_bfloat16* __restrict__ hi, __nv_bfloat16* __restrict__ lo)
{
    long i = (long)blockIdx.x * blockDim.x + threadIdx.x;
    if (i >= total) return;
    __nv_bfloat16 h, l; split_bf16(src[i], h, l);
    hi[i] = h; lo[i] = l;
}

#define C1 ((long)NXD * DIM)
#define C2 (C1 + (long)DIM * DTRK)
#define C3 (C2 + (long)DD * DIM)
__global__ __launch_bounds__(256) void cvt_rest_kernel(
    const float* __restrict__ s0, const float* __restrict__ s1,
    const float* __restrict__ s2,
    __nv_bfloat16* __restrict__ h0, __nv_bfloat16* __restrict__ l0,
    __nv_bfloat16* __restrict__ h1, __nv_bfloat16* __restrict__ l1,
    __nv_bfloat16* __restrict__ h2, __nv_bfloat16* __restrict__ l2)
{
    long i = (long)blockIdx.x * blockDim.x + threadIdx.x;
    if (i >= C3) return;
    const float* s; __nv_bfloat16 *ph, *pl; long j;
    if (i < C1)      { s = s0; ph = h0; pl = l0; j = i; }
    else if (i < C2) { s = s1; ph = h1; pl = l1; j = i - C1; }
    else             { s = s2; ph = h2; pl = l2; j = i - C2; }
    __nv_bfloat16 h, l; split_bf16(s[j], h, l);
    ph[j] = h; pl[j] = l;
}

// ---------------- fused add + LayerNorm (emits residual + h hi/lo) ----------
__global__ __launch_bounds__(256) void addnorm_kernel(
    const float* __restrict__ x, const float* __restrict__ res,
    const float* __restrict__ w, const float* __restrict__ b,
    float* __restrict__ res_out,
    __nv_bfloat16* __restrict__ h_hi, __nv_bfloat16* __restrict__ h_lo)
{
    const int row = blockIdx.x;
    const int tid = threadIdx.x;
    const float4* xv = reinterpret_cast<const float4*>(x + (size_t)row * DD);
    const float4* rv = reinterpret_cast<const float4*>(res + (size_t)row * DD);
    float4 a = xv[tid], r = rv[tid];
    float4 v = make_float4(a.x + r.x, a.y + r.y, a.z + r.z, a.w + r.w);
    reinterpret_cast<float4*>(res_out + (size_t)row * DD)[tid] = v;

    float s  = v.x + v.y + v.z + v.w;
    float ss = v.x*v.x + v.y*v.y + v.z*v.z + v.w*v.w;
    __shared__ float red[16];
    #pragma unroll
    for (int o = 16; o > 0; o >>= 1) {
        s  += __shfl_xor_sync(0xFFFFFFFFu, s,  o);
        ss += __shfl_xor_sync(0xFFFFFFFFu, ss, o);
    }
    int wid = tid >> 5, lane = tid & 31;
    if (lane == 0) { red[wid] = s; red[8 + wid] = ss; }
    __syncthreads();
    if (tid == 0) {
        float ts = 0.f, tss = 0.f;
        #pragma unroll
        for (int i = 0; i < 8; i++) { ts += red[i]; tss += red[8 + i]; }
        float mean = ts * (1.f / DD);
        float var  = tss * (1.f / DD) - mean * mean;
        red[0] = mean; red[1] = rsqrtf(var + 1e-5f);
    }
    __syncthreads();
    float mean = red[0], rstd = red[1];
    float4 wv = reinterpret_cast<const float4*>(w)[tid];
    float4 bv = reinterpret_cast<const float4*>(b)[tid];
    float hv[4];
    hv[0] = (v.x - mean) * rstd * wv.x + bv.x;
    hv[1] = (v.y - mean) * rstd * wv.y + bv.y;
    hv[2] = (v.z - mean) * rstd * wv.z + bv.z;
    hv[3] = (v.w - mean) * rstd * wv.w + bv.w;
    __nv_bfloat16 hh[4], ll[4];
    #pragma unroll
    for (int i = 0; i < 4; i++) split_bf16(hv[i], hh[i], ll[i]);
    size_t o = (size_t)row * DD + tid * 4;
    *reinterpret_cast<uint2*>(h_hi + o) = *reinterpret_cast<uint2*>(hh);
    *reinterpret_cast<uint2*>(h_lo + o) = *reinterpret_cast<uint2*>(ll);
}

// ---------------- causal depthwise conv (DC=4) + SiLU ------------------------
__global__ __launch_bounds__(256) void conv_silu_kernel(
    const float* __restrict__ xz, const float* __restrict__ cw,
    const float* __restrict__ cb, float* __restrict__ xc,
    __nv_bfloat16* __restrict__ xc_hi, __nv_bfloat16* __restrict__ xc_lo)
{
    int idx = blockIdx.x * blockDim.x + threadIdx.x;
    if (idx >= BB * LL * DIM) return;
    int d = idx % DIM;
    int t = (idx / DIM) % LL;
    int b = idx / (DIM * LL);
    float w0 = cw[d * 4 + 0], w1 = cw[d * 4 + 1];
    float w2 = cw[d * 4 + 2], w3 = cw[d * 4 + 3];
    size_t base = ((size_t)(b * LL + t)) * (2 * DIM) + d;
    float acc = cb[d];
    if (t >= 3) acc = fmaf(xz[base - 3 * (size_t)(2 * DIM)], w0, acc);
    if (t >= 2) acc = fmaf(xz[base - 2 * (size_t)(2 * DIM)], w1, acc);
    if (t >= 1) acc = fmaf(xz[base - 1 * (size_t)(2 * DIM)], w2, acc);
    acc = fmaf(xz[base], w3, acc);
    float sg = 1.f / (1.f + __expf(-acc));
    float v = acc * sg;
    xc[idx] = v;
    __nv_bfloat16 h, l; split_bf16(v, h, l);
    xc_hi[idx] = h; xc_lo[idx] = l;
}

// ---------------- chunked selective scan --------------------------------------
#define CH 32

__global__ __launch_bounds__(128) void scan_pass1(
    const float* __restrict__ xdbl, const float* __restrict__ dtraw,
    const float* __restrict__ dtb, const float* __restrict__ xc,
    const float* __restrict__ A_log,
    float* __restrict__ hend, float* __restrict__ Pbuf)
{
    const int b = blockIdx.z, c = blockIdx.y;
    const int d = blockIdx.x * 128 + threadIdx.x;
    float a[DS], h[DS];
    #pragma unroll
    for (int s = 0; s < DS; s++) {
        a[s] = -__expf(A_log[(size_t)d * DS + s]);
        h[s] = 0.f;
    }
    const float bias = dtb[d];
    float sumdt = 0.f;
    __shared__ float sB[CH][DS];
    const int tbase = c * CS;

    for (int t0 = 0; t0 < CS; t0 += CH) {
        __syncthreads();
        for (int idx = threadIdx.x; idx < CH * DS; idx += 128) {
            int r = idx >> 4, col = idx & 15;
            sB[r][col] = xdbl[(size_t)(b * LL + tbase + t0 + r) * NXD + DTRK + col];
        }
        __syncthreads();
        #pragma unroll 4
        for (int r = 0; r < CH; r++) {
            size_t off = (size_t)(b * LL + tbase + t0 + r) * DIM + d;
            float dtv = softplus_f(dtraw[off] + bias);
            sumdt += dtv;
            float dtx = dtv * xc[off];
            #pragma unroll
            for (int s = 0; s < DS; s++)
                h[s] = fmaf(__expf(dtv * a[s]), h[s], dtx * sB[r][s]);
        }
    }
    size_t obase = ((size_t)(b * NC + c) * DS) * DIM + d;
    #pragma unroll
    for (int s = 0; s < DS; s++) {
        hend[obase + (size_t)s * DIM] = h[s];
        Pbuf[obase + (size_t)s * DIM] = __expf(a[s] * sumdt);
    }
}

__global__ __launch_bounds__(128) void scan_pass2(
    const float* __restrict__ hend, const float* __restrict__ Pbuf,
    float* __restrict__ h0buf)
{
    const int b = blockIdx.y;
    const int d = blockIdx.x * 128 + threadIdx.x;
    float h0[DS];
    #pragma unroll
    for (int s = 0; s < DS; s++) h0[s] = 0.f;
    for (int c = 0; c < NC; c++) {
        size_t base = ((size_t)(b * NC + c) * DS) * DIM + d;
        #pragma unroll
        for (int s = 0; s < DS; s++) {
            h0buf[base + (size_t)s * DIM] = h0[s];
            h0[s] = fmaf(Pbuf[base + (size_t)s * DIM], h0[s],
                         hend[base + (size_t)s * DIM]);
        }
    }
}

__global__ __launch_bounds__(128) void scan_pass3(
    const float* __restrict__ xdbl, const float* __restrict__ dtraw,
    const float* __restrict__ dtb, const float* __restrict__ xc,
    const float* __restrict__ xz, const float* __restrict__ A_log,
    const float* __restrict__ Dp, const float* __restrict__ h0buf,
    __nv_bfloat16* __restrict__ y_hi, __nv_bfloat16* __restrict__ y_lo)
{
    const int b = blockIdx.z, c = blockIdx.y;
    const int d = blockIdx.x * 128 + threadIdx.x;
    float a[DS], h[DS];
    size_t hbase = ((size_t)(b * NC + c) * DS) * DIM + d;
    #pragma unroll
    for (int s = 0; s < DS; s++) {
        a[s] = -__expf(A_log[(size_t)d * DS + s]);
        h[s] = h0buf[hbase + (size_t)s * DIM];
    }
    const float Dd   = Dp[d];
    const float bias = dtb[d];
    __shared__ float sB[CH][DS];
    __shared__ float sC[CH][DS];
    const int tbase = c * CS;

    for (int t0 = 0; t0 < CS; t0 += CH) {
        __syncthreads();
        for (int idx = threadIdx.x; idx < CH * 32; idx += 128) {
            int r = idx >> 5, col = idx & 31;
            float v = xdbl[(size_t)(b * LL + tbase + t0 + r) * NXD + DTRK + col];
            if (col < DS) sB[r][col] = v; else sC[r][col - DS] = v;
        }
        __syncthreads();
        #pragma unroll 4
        for (int r = 0; r < CH; r++) {
            int t = tbase + t0 + r;
            size_t off = (size_t)(b * LL + t) * DIM + d;
            float dtv = softplus_f(dtraw[off] + bias);
            float x = xc[off];
            float z = xz[(size_t)(b * LL + t) * (2 * DIM) + DIM + d];
            float dtx = dtv * x;
            float y = 0.f;
            #pragma unroll
            for (int s = 0; s < DS; s++) {
                h[s] = fmaf(__expf(dtv * a[s]), h[s], dtx * sB[r][s]);
                y = fmaf(h[s], sC[r][s], y);
            }
            float sz = z / (1.f + __expf(-z));
            float yo = (y + Dd * x) * sz;
            __nv_bfloat16 hh, ll; split_bf16(yo, hh, ll);
            y_hi[off] = hh; y_lo[off] = ll;
        }
    }
}

// ---------------- launch ------------------------------------------------------
extern "C" void kernel_launch(void* const* d_in, const int* in_sizes, int n_in,
                              void* d_out, int out_size)
{
    const float* x          = (const float*)d_in[0];
    const float* residual   = (const float*)d_in[1];
    const float* ln_w       = (const float*)d_in[2];
    const float* ln_b       = (const float*)d_in[3];
    const float* in_proj_w  = (const float*)d_in[4];
    const float* conv_w     = (const float*)d_in[5];
    const float* conv_b     = (const float*)d_in[6];
    const float* x_proj_w   = (const float*)d_in[7];
    const float* dt_proj_w  = (const float*)d_in[8];
    const float* dt_proj_b  = (const float*)d_in[9];
    const float* A_log      = (const float*)d_in[10];
    const float* D_param    = (const float*)d_in[11];
    const float* out_proj_w = (const float*)d_in[12];

    float* out     = (float*)d_out;
    float* res_out = out + (size_t)BL * DD;

    float *xz, *xc, *xdbl, *xpart, *dtraw, *hend, *Pbuf, *h0buf;
    __nv_bfloat16 *h_hi, *h_lo, *wi_hi, *wi_lo, *xc_hi, *xc_lo, *xp_hi, *xp_lo;
    __nv_bfloat16 *dta_hi, *dta_lo, *dtw_hi, *dtw_lo, *y_hi, *y_lo, *ow_hi, *ow_lo;
    cudaGetSymbolAddress((void**)&xz,    g_xz);
    cudaGetSymbolAddress((void**)&xc,    g_xc);
    cudaGetSymbolAddress((void**)&xdbl,  g_xdbl);
    cudaGetSymbolAddress((void**)&xpart, g_xpart);
    cudaGetSymbolAddress((void**)&dtraw, g_dtraw);
    cudaGetSymbolAddress((void**)&hend,  g_hend);
    cudaGetSymbolAddress((void**)&Pbuf,  g_P);
    cudaGetSymbolAddress((void**)&h0buf, g_h0);
    cudaGetSymbolAddress((void**)&h_hi,  g_h_hi);  cudaGetSymbolAddress((void**)&h_lo,  g_h_lo);
    cudaGetSymbolAddress((void**)&wi_hi, g_wi_hi); cudaGetSymbolAddress((void**)&wi_lo, g_wi_lo);
    cudaGetSymbolAddress((void**)&xc_hi, g_xc_hi); cudaGetSymbolAddress((void**)&xc_lo, g_xc_lo);
    cudaGetSymbolAddress((void**)&xp_hi, g_xp_hi); cudaGetSymbolAddress((void**)&xp_lo, g_xp_lo);
    cudaGetSymbolAddress((void**)&dta_hi,g_dta_hi);cudaGetSymbolAddress((void**)&dta_lo,g_dta_lo);
    cudaGetSymbolAddress((void**)&dtw_hi,g_dtw_hi);cudaGetSymbolAddress((void**)&dtw_lo,g_dtw_lo);
    cudaGetSymbolAddress((void**)&y_hi,  g_y_hi);  cudaGetSymbolAddress((void**)&y_lo,  g_y_lo);
    cudaGetSymbolAddress((void**)&ow_hi, g_ow_hi); cudaGetSymbolAddress((void**)&ow_lo, g_ow_lo);

    cudaFuncSetAttribute(tc_gemm, cudaFuncAttributeMaxDynamicSharedMemorySize, GSMEM);

    // 0) in_proj weight cvt
    {
        long t1 = (long)2 * DIM * DD;
        cvt_flat_kernel<<<(int)((t1 + 255) / 256), 256>>>(in_proj_w, t1, wi_hi, wi_lo);
    }
    // 1) remaining weights (fused)
    cvt_rest_kernel<<<(int)((C3 + 255) / 256), 256>>>(
        x_proj_w, dt_proj_w, out_proj_w,
        xp_hi, xp_lo, dtw_hi, dtw_lo, ow_hi, ow_lo);

    // 2) residual = x + residual; h = LN(residual) -> hi/lo
    addnorm_kernel<<<BL, 256>>>(x, residual, ln_w, ln_b, res_out, h_hi, h_lo);

    // 3) xz = h @ in_proj_w^T   (M=4096, N=4096, K=1024)   <-- ncu window
    tc_gemm<<<dim3(2 * DIM / 128, BL / 128), 256, GSMEM>>>(
        h_hi, h_lo, wi_hi, wi_lo, xz, 2 * DIM, 2 * DIM, DD, DD, 0,
        ((__nv_bfloat16*)0), ((__nv_bfloat16*)0), 0);

    // 4) xc = silu(causal_conv(x_in))
    conv_silu_kernel<<<(BB * LL * DIM + 255) / 256, 256>>>(xz, conv_w, conv_b, xc, xc_hi, xc_lo);

    // 5) x_dbl = xc @ x_proj_w^T (M=4096, N=96, K=2048), 8-way split-K + reduce
    tc_gemm<<<dim3(1, BL / 128, KSPL), 256, GSMEM>>>(
        xc_hi, xc_lo, xp_hi, xp_lo, xpart, NXD, NXD, DIM, DIM / KSPL,
        (long)BL * NXD, ((__nv_bfloat16*)0), ((__nv_bfloat16*)0), 0);
    xpart_reduce_kernel<<<(BL * NXD + 255) / 256, 256>>>(xpart, xdbl, dta_hi, dta_lo);

    // 6) dt_raw = dt_r @ dt_proj_w^T   (M=4096, N=2048, K=64)
    tc_gemm<<<dim3(DIM / 128, BL / 128), 256, GSMEM>>>(
        dta_hi, dta_lo, dtw_hi, dtw_lo, dtraw, DIM, DIM, DTRK, DTRK, 0,
        ((__nv_bfloat16*)0), ((__nv_bfloat16*)0), 0);

    // 7) chunked selective scan
    scan_pass1<<<dim3(DIM / 128, NC, BB), 128>>>(
        xdbl, dtraw, dt_proj_b, xc, A_log, hend, Pbuf);
    scan_pass2<<<dim3(DIM / 128, BB), 128>>>(hend, Pbuf, h0buf);
    scan_pass3<<<dim3(DIM / 128, NC, BB), 128>>>(
        xdbl, dtraw, dt_proj_b, xc, xz, A_log, D_param, h0buf, y_hi, y_lo);

    // 8) out = y @ out_proj_w^T   (M=4096, N=1024, K=2048)
    tc_gemm<<<dim3(DD / 128, BL / 128), 256, GSMEM>>>(
        y_hi, y_lo, ow_hi, ow_lo, out, DD, DD, DIM, DIM, 0,
        ((__nv_bfloat16*)0), ((__nv_bfloat16*)0), 0);
}

// round 9
// speedup vs baseline: 4.7285x; 1.0834x over previous
#include <cuda_runtime.h>
#include <cuda_bf16.h>
#include <cstdint>
#include <math.h>

// Problem constants
#define BB   2
#define LL   2048
#define DD   1024
#define DIM  2048      // d_inner
#define DS   16        // d_state
#define DTRK 64        // dt_rank
#define NXD  96        // DTR + 2*DS
#define BL   (BB*LL)   // 4096 rows
#define NC   16        // scan chunks
#define CS   (LL/NC)   // 128 steps per chunk
#define KSPL 8         // x_proj split-K factor

// ---------------- scratch (device globals; no runtime allocation) ----------
__device__ __align__(256) float g_xz[(size_t)BL * 2 * DIM];
__device__ __align__(256) float g_xc[(size_t)BL * DIM];
__device__ __align__(256) float g_xdbl[(size_t)BL * NXD];
__device__ __align__(256) float g_xpart[(size_t)KSPL * BL * NXD];
__device__ __align__(256) float g_dtraw[(size_t)BL * DIM];   // dt linear -> dtv (in-place)
__device__ __align__(256) float g_hend[(size_t)BB * NC * DS * DIM];
__device__ __align__(256) float g_P[(size_t)BB * NC * DS * DIM];

__device__ __align__(256) __nv_bfloat16 g_h_hi[(size_t)BL * DD],    g_h_lo[(size_t)BL * DD];
__device__ __align__(256) __nv_bfloat16 g_wi_hi[(size_t)2*DIM*DD],  g_wi_lo[(size_t)2*DIM*DD];
__device__ __align__(256) __nv_bfloat16 g_xc_hi[(size_t)BL * DIM],  g_xc_lo[(size_t)BL * DIM];
__device__ __align__(256) __nv_bfloat16 g_xp_hi[(size_t)NXD * DIM], g_xp_lo[(size_t)NXD * DIM];
__device__ __align__(256) __nv_bfloat16 g_dta_hi[(size_t)BL * DTRK],g_dta_lo[(size_t)BL * DTRK];
__device__ __align__(256) __nv_bfloat16 g_dtw_hi[(size_t)DIM*DTRK], g_dtw_lo[(size_t)DIM*DTRK];
__device__ __align__(256) __nv_bfloat16 g_y_hi[(size_t)BL * DIM],   g_y_lo[(size_t)BL * DIM];
__device__ __align__(256) __nv_bfloat16 g_ow_hi[(size_t)DD * DIM],  g_ow_lo[(size_t)DD * DIM];

// ---------------- helpers ----------------------------------------------------
__device__ __forceinline__ uint32_t smem_u32(const void* p) {
    uint32_t a;
    asm("{ .reg .u64 t; cvta.to.shared.u64 t, %1; cvt.u32.u64 %0, t; }"
        : "=r"(a) : "l"(p));
    return a;
}
__device__ __forceinline__ void split_bf16(float v, __nv_bfloat16& hi, __nv_bfloat16& lo) {
    hi = __float2bfloat16(v);
    lo = __float2bfloat16(v - __bfloat162float(hi));
}
__device__ __forceinline__ float softplus_f(float x) {
    return (x > 20.f) ? x : log1pf(__expf(x));
}

__device__ __forceinline__ void ldm_x4(uint32_t addr, uint32_t r[4]) {
    asm volatile("ldmatrix.sync.aligned.m8n8.x4.shared.b16 {%0,%1,%2,%3}, [%4];"
        : "=r"(r[0]), "=r"(r[1]), "=r"(r[2]), "=r"(r[3]) : "r"(addr));
}
__device__ __forceinline__ void mma_bf16(float d[4], const uint32_t a[4],
                                         uint32_t b0, uint32_t b1) {
    asm volatile(
        "mma.sync.aligned.m16n8k16.row.col.f32.bf16.bf16.f32 "
        "{%0,%1,%2,%3}, {%4,%5,%6,%7}, {%8,%9}, {%0,%1,%2,%3};"
        : "+f"(d[0]), "+f"(d[1]), "+f"(d[2]), "+f"(d[3])
        : "r"(a[0]), "r"(a[1]), "r"(a[2]), "r"(a[3]), "r"(b0), "r"(b1));
}
__device__ __forceinline__ void cp16(uint32_t dst, const void* src, int srcsize) {
    asm volatile("cp.async.cg.shared.global [%0], [%1], 16, %2;"
                 :: "r"(dst), "l"(src), "r"(srcsize));
}
__device__ __forceinline__ void cp_commit() {
    asm volatile("cp.async.commit_group;");
}
__device__ __forceinline__ void cp_wait2() {
    asm volatile("cp.async.wait_group 2;");
}

// ---------------- split-bf16 tensor-core GEMM (mma.sync path) ----------------
#define TILEB 8192                 // 128 rows * 64 B
#define STAGE3 (4 * TILEB)         // 32768 B per stage
#define GSMEM (3 * STAGE3)         // 98304 B dynamic smem

__global__ __launch_bounds__(256, 2) void tc_gemm(
    const __nv_bfloat16* __restrict__ Ahi, const __nv_bfloat16* __restrict__ Alo,
    const __nv_bfloat16* __restrict__ Bhi, const __nv_bfloat16* __restrict__ Blo,
    float* __restrict__ C, int ldc, int N, int ldK, int Ksub, long cstride,
    __nv_bfloat16* __restrict__ Ehi, __nv_bfloat16* __restrict__ Elo, int ecols)
{
    extern __shared__ char smem[];
    const uint32_t sbase = smem_u32(smem);
    const int tid  = threadIdx.x;
    const int wid  = tid >> 5;
    const int lane = tid & 31;
    const int warp_m = wid & 3;
    const int warp_n = wid >> 2;
    const int m0 = blockIdx.y * 128;
    const int n0 = blockIdx.x * 128;
    const int kbase = blockIdx.z * Ksub;
    C += (long)blockIdx.z * cstride;

    const __nv_bfloat16* srcA[2] = { Ahi + (size_t)m0 * ldK + kbase,
                                     Alo + (size_t)m0 * ldK + kbase };
    const __nv_bfloat16* srcB[2] = { Bhi + (size_t)n0 * ldK + kbase,
                                     Blo + (size_t)n0 * ldK + kbase };

    float acc[2][8][4];
    #pragma unroll
    for (int a = 0; a < 2; a++)
        #pragma unroll
        for (int b = 0; b < 8; b++)
            #pragma unroll
            for (int c = 0; c < 4; c++) acc[a][b][c] = 0.f;

    const int nch = Ksub / 32;

    auto load_chunk = [&](int stage, int k0) {
        const uint32_t base = sbase + stage * STAGE3;
        #pragma unroll
        for (int i = 0; i < 8; i++) {
            const int tile = i >> 1;
            const int rem  = ((i & 1) << 8) + tid;
            const int row  = rem >> 2;
            const int c    = rem & 3;
            const int csw  = c ^ ((row >> 1) & 3);
            const uint32_t dst = base + tile * TILEB + row * 64 + csw * 16;
            const __nv_bfloat16* g;
            int sz = 16;
            if (tile < 2) {
                g = srcA[tile] + (size_t)row * ldK + k0 + c * 8;
            } else {
                g = srcB[tile - 2] + (size_t)row * ldK + k0 + c * 8;
                if (n0 + row >= N) sz = 0;
            }
            cp16(dst, g, sz);
        }
    };

    load_chunk(0, 0);
    cp_commit();
    if (1 < nch) load_chunk(1, 32);
    cp_commit();

    for (int ch = 0; ch < nch; ch++) {
        if (ch + 2 < nch) load_chunk((ch + 2) % 3, (ch + 2) * 32);
        cp_commit();
        cp_wait2();
        __syncthreads();

        const uint32_t st = sbase + (ch % 3) * STAGE3;
        const uint32_t aHiB = st;
        const uint32_t aLoB = st + TILEB;
        const uint32_t bHiB = st + 2 * TILEB;
        const uint32_t bLoB = st + 3 * TILEB;

        #pragma unroll
        for (int k16 = 0; k16 < 2; k16++) {
            uint32_t ah[2][4], al[2][4], bh[4][4], bl[4][4];
            const int ci = k16 * 2 + (lane >> 4);
            #pragma unroll
            for (int mf = 0; mf < 2; mf++) {
                const int row = warp_m * 32 + mf * 16 + (lane & 15);
                const uint32_t off = row * 64 + ((ci ^ ((row >> 1) & 3)) * 16);
                ldm_x4(aHiB + off, ah[mf]);
                ldm_x4(aLoB + off, al[mf]);
            }
            #pragma unroll
            for (int nb = 0; nb < 4; nb++) {
                const int rowb = warp_n * 64 + nb * 16 + (lane & 15);
                const uint32_t offb = rowb * 64 + ((ci ^ ((rowb >> 1) & 3)) * 16);
                ldm_x4(bHiB + offb, bh[nb]);
                ldm_x4(bLoB + offb, bl[nb]);
            }
            #pragma unroll
            for (int mf = 0; mf < 2; mf++)
                #pragma unroll
                for (int nb = 0; nb < 4; nb++) {
                    mma_bf16(acc[mf][nb*2],   ah[mf], bh[nb][0], bh[nb][2]);
                    mma_bf16(acc[mf][nb*2+1], ah[mf], bh[nb][1], bh[nb][3]);
                }
            #pragma unroll
            for (int mf = 0; mf < 2; mf++)
                #pragma unroll
                for (int nb = 0; nb < 4; nb++) {
                    mma_bf16(acc[mf][nb*2],   ah[mf], bl[nb][0], bl[nb][2]);
                    mma_bf16(acc[mf][nb*2+1], ah[mf], bl[nb][1], bl[nb][3]);
                }
            #pragma unroll
            for (int mf = 0; mf < 2; mf++)
                #pragma unroll
                for (int nb = 0; nb < 4; nb++) {
                    mma_bf16(acc[mf][nb*2],   al[mf], bh[nb][0], bh[nb][2]);
                    mma_bf16(acc[mf][nb*2+1], al[mf], bh[nb][1], bh[nb][3]);
                }
        }
        __syncthreads();
    }

    #pragma unroll
    for (int mf = 0; mf < 2; mf++) {
        #pragma unroll
        for (int nf = 0; nf < 8; nf++) {
            const int r0  = m0 + warp_m * 32 + mf * 16 + (lane >> 2);
            const int col = n0 + warp_n * 64 + nf * 8 + (lane & 3) * 2;
            if (col < N) {
                float2 v0 = make_float2(acc[mf][nf][0], acc[mf][nf][1]);
                float2 v1 = make_float2(acc[mf][nf][2], acc[mf][nf][3]);
                *reinterpret_cast<float2*>(C + (size_t)r0 * ldc + col) = v0;
                *reinterpret_cast<float2*>(C + (size_t)(r0 + 8) * ldc + col) = v1;
                if (Ehi && col < ecols) {
                    __nv_bfloat16 h0, l0, h1, l1;
                    split_bf16(v0.x, h0, l0); split_bf16(v0.y, h1, l1);
                    __nv_bfloat162 hh = __nv_bfloat162(h0, h1);
                    __nv_bfloat162 ll = __nv_bfloat162(l0, l1);
                    *reinterpret_cast<__nv_bfloat162*>(Ehi + (size_t)r0 * ecols + col) = hh;
                    *reinterpret_cast<__nv_bfloat162*>(Elo + (size_t)r0 * ecols + col) = ll;
                    split_bf16(v1.x, h0, l0); split_bf16(v1.y, h1, l1);
                    hh = __nv_bfloat162(h0, h1); ll = __nv_bfloat162(l0, l1);
                    *reinterpret_cast<__nv_bfloat162*>(Ehi + (size_t)(r0+8) * ecols + col) = hh;
                    *reinterpret_cast<__nv_bfloat162*>(Elo + (size_t)(r0+8) * ecols + col) = ll;
                }
            }
        }
    }
}

// ---------------- split-K reduce for x_proj + fused dt-slice cvt -------------
__global__ __launch_bounds__(256) void xpart_reduce_kernel(
    const float* __restrict__ part, float* __restrict__ xdbl,
    __nv_bfloat16* __restrict__ dta_hi, __nv_bfloat16* __restrict__ dta_lo)
{
    int i = blockIdx.x * blockDim.x + threadIdx.x;
    if (i >= BL * NXD) return;
    float s = 0.f;
    #pragma unroll
    for (int z = 0; z < KSPL; z++) s += part[(size_t)z * BL * NXD + i];
    xdbl[i] = s;
    int col = i % NXD;
    if (col < DTRK) {
        int row = i / NXD;
        __nv_bfloat16 h, l; split_bf16(s, h, l);
        dta_hi[(size_t)row * DTRK + col] = h;
        dta_lo[(size_t)row * DTRK + col] = l;
    }
}

// ---------------- weight conversions ----------------------------------------
__global__ __launch_bounds__(256) void cvt_flat_kernel(
    const float* __restrict__ src, long total,
    __nv_bfloat16* __restrict__ hi, __nv_bfloat16* __restrict__ lo)
{
    long i = (long)blockIdx.x * blockDim.x + threadIdx.x;
    if (i >= total) return;
    __nv_bfloat16 h, l; split_bf16(src[i], h, l);
    hi[i] = h; lo[i] = l;
}

#define C1 ((long)NXD * DIM)
#define C2 (C1 + (long)DIM * DTRK)
#define C3 (C2 + (long)DD * DIM)
__global__ __launch_bounds__(256) void cvt_rest_kernel(
    const float* __restrict__ s0, const float* __restrict__ s1,
    const float* __restrict__ s2,
    __nv_bfloat16* __restrict__ h0, __nv_bfloat16* __restrict__ l0,
    __nv_bfloat16* __restrict__ h1, __nv_bfloat16* __restrict__ l1,
    __nv_bfloat16* __restrict__ h2, __nv_bfloat16* __restrict__ l2)
{
    long i = (long)blockIdx.x * blockDim.x + threadIdx.x;
    if (i >= C3) return;
    const float* s; __nv_bfloat16 *ph, *pl; long j;
    if (i < C1)      { s = s0; ph = h0; pl = l0; j = i; }
    else if (i < C2) { s = s1; ph = h1; pl = l1; j = i - C1; }
    else             { s = s2; ph = h2; pl = l2; j = i - C2; }
    __nv_bfloat16 h, l; split_bf16(s[j], h, l);
    ph[j] = h; pl[j] = l;
}

// ---------------- fused add + LayerNorm (emits residual + h hi/lo) ----------
__global__ __launch_bounds__(256) void addnorm_kernel(
    const float* __restrict__ x, const float* __restrict__ res,
    const float* __restrict__ w, const float* __restrict__ b,
    float* __restrict__ res_out,
    __nv_bfloat16* __restrict__ h_hi, __nv_bfloat16* __restrict__ h_lo)
{
    const int row = blockIdx.x;
    const int tid = threadIdx.x;
    const float4* xv = reinterpret_cast<const float4*>(x + (size_t)row * DD);
    const float4* rv = reinterpret_cast<const float4*>(res + (size_t)row * DD);
    float4 a = xv[tid], r = rv[tid];
    float4 v = make_float4(a.x + r.x, a.y + r.y, a.z + r.z, a.w + r.w);
    reinterpret_cast<float4*>(res_out + (size_t)row * DD)[tid] = v;

    float s  = v.x + v.y + v.z + v.w;
    float ss = v.x*v.x + v.y*v.y + v.z*v.z + v.w*v.w;
    __shared__ float red[16];
    #pragma unroll
    for (int o = 16; o > 0; o >>= 1) {
        s  += __shfl_xor_sync(0xFFFFFFFFu, s,  o);
        ss += __shfl_xor_sync(0xFFFFFFFFu, ss, o);
    }
    int wid = tid >> 5, lane = tid & 31;
    if (lane == 0) { red[wid] = s; red[8 + wid] = ss; }
    __syncthreads();
    if (tid == 0) {
        float ts = 0.f, tss = 0.f;
        #pragma unroll
        for (int i = 0; i < 8; i++) { ts += red[i]; tss += red[8 + i]; }
        float mean = ts * (1.f / DD);
        float var  = tss * (1.f / DD) - mean * mean;
        red[0] = mean; red[1] = rsqrtf(var + 1e-5f);
    }
    __syncthreads();
    float mean = red[0], rstd = red[1];
    float4 wv = reinterpret_cast<const float4*>(w)[tid];
    float4 bv = reinterpret_cast<const float4*>(b)[tid];
    float hv[4];
    hv[0] = (v.x - mean) * rstd * wv.x + bv.x;
    hv[1] = (v.y - mean) * rstd * wv.y + bv.y;
    hv[2] = (v.z - mean) * rstd * wv.z + bv.z;
    hv[3] = (v.w - mean) * rstd * wv.w + bv.w;
    __nv_bfloat16 hh[4], ll[4];
    #pragma unroll
    for (int i = 0; i < 4; i++) split_bf16(hv[i], hh[i], ll[i]);
    size_t o = (size_t)row * DD + tid * 4;
    *reinterpret_cast<uint2*>(h_hi + o) = *reinterpret_cast<uint2*>(hh);
    *reinterpret_cast<uint2*>(h_lo + o) = *reinterpret_cast<uint2*>(ll);
}

// ---------------- causal depthwise conv (DC=4) + SiLU ------------------------
__global__ __launch_bounds__(256) void conv_silu_kernel(
    const float* __restrict__ xz, const float* __restrict__ cw,
    const float* __restrict__ cb, float* __restrict__ xc,
    __nv_bfloat16* __restrict__ xc_hi, __nv_bfloat16* __restrict__ xc_lo)
{
    int idx = blockIdx.x * blockDim.x + threadIdx.x;
    if (idx >= BB * LL * DIM) return;
    int d = idx % DIM;
    int t = (idx / DIM) % LL;
    int b = idx / (DIM * LL);
    float w0 = cw[d * 4 + 0], w1 = cw[d * 4 + 1];
    float w2 = cw[d * 4 + 2], w3 = cw[d * 4 + 3];
    size_t base = ((size_t)(b * LL + t)) * (2 * DIM) + d;
    float acc = cb[d];
    if (t >= 3) acc = fmaf(xz[base - 3 * (size_t)(2 * DIM)], w0, acc);
    if (t >= 2) acc = fmaf(xz[base - 2 * (size_t)(2 * DIM)], w1, acc);
    if (t >= 1) acc = fmaf(xz[base - 1 * (size_t)(2 * DIM)], w2, acc);
    acc = fmaf(xz[base], w3, acc);
    float sg = 1.f / (1.f + __expf(-acc));
    float v = acc * sg;
    xc[idx] = v;
    __nv_bfloat16 h, l; split_bf16(v, h, l);
    xc_hi[idx] = h; xc_lo[idx] = l;
}

// ---------------- chunked selective scan --------------------------------------
// S4D structure: A_log rows are log(1..16) -> a[s] = -(s+1); then
// exp(dtv*a[s]) = E^(s+1) with E = exp(-dtv): 1 MUFU + 15 FMUL per step.
// Verified per-thread (pow_ok) with generic per-s __expf fallback.
// pass1 also stores dtv = softplus(dtraw+bias) in-place into dtraw.
// pass2 is folded into pass3 (local prefix combine from hend/P).
#define CH 32

__global__ __launch_bounds__(128) void scan_pass1(
    const float* __restrict__ xdbl, float* __restrict__ dtraw,
    const float* __restrict__ dtb, const float* __restrict__ xc,
    const float* __restrict__ A_log,
    float* __restrict__ hend, float* __restrict__ Pbuf)
{
    const int b = blockIdx.z, c = blockIdx.y;
    const int d = blockIdx.x * 128 + threadIdx.x;
    float a[DS], h[DS];
    bool pow_ok = true;
    #pragma unroll
    for (int s = 0; s < DS; s++) {
        a[s] = -__expf(A_log[(size_t)d * DS + s]);
        pow_ok = pow_ok && (fabsf(-a[s] - (float)(s + 1)) < 1e-3f);
        h[s] = 0.f;
    }
    const float bias = dtb[d];
    float sumdt = 0.f;
    __shared__ float sB[CH][DS];
    const int tbase = c * CS;

    for (int t0 = 0; t0 < CS; t0 += CH) {
        __syncthreads();
        for (int idx = threadIdx.x; idx < CH * DS; idx += 128) {
            int r = idx >> 4, col = idx & 15;
            sB[r][col] = xdbl[(size_t)(b * LL + tbase + t0 + r) * NXD + DTRK + col];
        }
        __syncthreads();
        if (pow_ok) {
            #pragma unroll 4
            for (int r = 0; r < CH; r++) {
                size_t off = (size_t)(b * LL + tbase + t0 + r) * DIM + d;
                float dtv = softplus_f(dtraw[off] + bias);
                dtraw[off] = dtv;
                sumdt += dtv;
                float dtx = dtv * xc[off];
                float E = __expf(-dtv);
                float p = E;
                #pragma unroll
                for (int s = 0; s < DS; s++) {
                    h[s] = fmaf(p, h[s], dtx * sB[r][s]);
                    p *= E;
                }
            }
        } else {
            #pragma unroll 4
            for (int r = 0; r < CH; r++) {
                size_t off = (size_t)(b * LL + tbase + t0 + r) * DIM + d;
                float dtv = softplus_f(dtraw[off] + bias);
                dtraw[off] = dtv;
                sumdt += dtv;
                float dtx = dtv * xc[off];
                #pragma unroll
                for (int s = 0; s < DS; s++)
                    h[s] = fmaf(__expf(dtv * a[s]), h[s], dtx * sB[r][s]);
            }
        }
    }
    size_t obase = ((size_t)(b * NC + c) * DS) * DIM + d;
    if (pow_ok) {
        float Es = __expf(-sumdt);
        float p = Es;
        #pragma unroll
        for (int s = 0; s < DS; s++) {
            hend[obase + (size_t)s * DIM] = h[s];
            Pbuf[obase + (size_t)s * DIM] = p;
            p *= Es;
        }
    } else {
        #pragma unroll
        for (int s = 0; s < DS; s++) {
            hend[obase + (size_t)s * DIM] = h[s];
            Pbuf[obase + (size_t)s * DIM] = __expf(a[s] * sumdt);
        }
    }
}

__global__ __launch_bounds__(128) void scan_pass3(
    const float* __restrict__ xdbl, const float* __restrict__ dtv_buf,
    const float* __restrict__ xc, const float* __restrict__ xz,
    const float* __restrict__ A_log, const float* __restrict__ Dp,
    const float* __restrict__ hend, const float* __restrict__ Pbuf,
    __nv_bfloat16* __restrict__ y_hi, __nv_bfloat16* __restrict__ y_lo)
{
    const int b = blockIdx.z, c = blockIdx.y;
    const int d = blockIdx.x * 128 + threadIdx.x;
    float a[DS], h[DS];
    bool pow_ok = true;
    #pragma unroll
    for (int s = 0; s < DS; s++) {
        a[s] = -__expf(A_log[(size_t)d * DS + s]);
        pow_ok = pow_ok && (fabsf(-a[s] - (float)(s + 1)) < 1e-3f);
        h[s] = 0.f;
    }
    // local prefix combine over chunks 0..c-1
    for (int cc = 0; cc < c; cc++) {
        size_t base = ((size_t)(b * NC + cc) * DS) * DIM + d;
        #pragma unroll
        for (int s = 0; s < DS; s++)
            h[s] = fmaf(Pbuf[base + (size_t)s * DIM], h[s],
                        hend[base + (size_t)s * DIM]);
    }
    const float Dd = Dp[d];
    __shared__ float sB[CH][DS];
    __shared__ float sC[CH][DS];
    const int tbase = c * CS;

    for (int t0 = 0; t0 < CS; t0 += CH) {
        __syncthreads();
        for (int idx = threadIdx.x; idx < CH * 32; idx += 128) {
            int r = idx >> 5, col = idx & 31;
            float v = xdbl[(size_t)(b * LL + tbase + t0 + r) * NXD + DTRK + col];
            if (col < DS) sB[r][col] = v; else sC[r][col - DS] = v;
        }
        __syncthreads();
        if (pow_ok) {
            #pragma unroll 4
            for (int r = 0; r < CH; r++) {
                int t = tbase + t0 + r;
                size_t off = (size_t)(b * LL + t) * DIM + d;
                float dtv = dtv_buf[off];
                float x = xc[off];
                float z = xz[(size_t)(b * LL + t) * (2 * DIM) + DIM + d];
                float dtx = dtv * x;
                float y = 0.f;
                float E = __expf(-dtv);
                float p = E;
                #pragma unroll
                for (int s = 0; s < DS; s++) {
                    h[s] = fmaf(p, h[s], dtx * sB[r][s]);
                    y = fmaf(h[s], sC[r][s], y);
                    p *= E;
                }
                float sz = z / (1.f + __expf(-z));
                float yo = (y + Dd * x) * sz;
                __nv_bfloat16 hh, ll; split_bf16(yo, hh, ll);
                y_hi[off] = hh; y_lo[off] = ll;
            }
        } else {
            #pragma unroll 4
            for (int r = 0; r < CH; r++) {
                int t = tbase + t0 + r;
                size_t off = (size_t)(b * LL + t) * DIM + d;
                float dtv = dtv_buf[off];
                float x = xc[off];
                float z = xz[(size_t)(b * LL + t) * (2 * DIM) + DIM + d];
                float dtx = dtv * x;
                float y = 0.f;
                #pragma unroll
                for (int s = 0; s < DS; s++) {
                    h[s] = fmaf(__expf(dtv * a[s]), h[s], dtx * sB[r][s]);
                    y = fmaf(h[s], sC[r][s], y);
                }
                float sz = z / (1.f + __expf(-z));
                float yo = (y + Dd * x) * sz;
                __nv_bfloat16 hh, ll; split_bf16(yo, hh, ll);
                y_hi[off] = hh; y_lo[off] = ll;
            }
        }
    }
}

// ---------------- launch ------------------------------------------------------
extern "C" void kernel_launch(void* const* d_in, const int* in_sizes, int n_in,
                              void* d_out, int out_size)
{
    const float* x          = (const float*)d_in[0];
    const float* residual   = (const float*)d_in[1];
    const float* ln_w       = (const float*)d_in[2];
    const float* ln_b       = (const float*)d_in[3];
    const float* in_proj_w  = (const float*)d_in[4];
    const float* conv_w     = (const float*)d_in[5];
    const float* conv_b     = (const float*)d_in[6];
    const float* x_proj_w   = (const float*)d_in[7];
    const float* dt_proj_w  = (const float*)d_in[8];
    const float* dt_proj_b  = (const float*)d_in[9];
    const float* A_log      = (const float*)d_in[10];
    const float* D_param    = (const float*)d_in[11];
    const float* out_proj_w = (const float*)d_in[12];

    float* out     = (float*)d_out;
    float* res_out = out + (size_t)BL * DD;

    float *xz, *xc, *xdbl, *xpart, *dtraw, *hend, *Pbuf;
    __nv_bfloat16 *h_hi, *h_lo, *wi_hi, *wi_lo, *xc_hi, *xc_lo, *xp_hi, *xp_lo;
    __nv_bfloat16 *dta_hi, *dta_lo, *dtw_hi, *dtw_lo, *y_hi, *y_lo, *ow_hi, *ow_lo;
    cudaGetSymbolAddress((void**)&xz,    g_xz);
    cudaGetSymbolAddress((void**)&xc,    g_xc);
    cudaGetSymbolAddress((void**)&xdbl,  g_xdbl);
    cudaGetSymbolAddress((void**)&xpart, g_xpart);
    cudaGetSymbolAddress((void**)&dtraw, g_dtraw);
    cudaGetSymbolAddress((void**)&hend,  g_hend);
    cudaGetSymbolAddress((void**)&Pbuf,  g_P);
    cudaGetSymbolAddress((void**)&h_hi,  g_h_hi);  cudaGetSymbolAddress((void**)&h_lo,  g_h_lo);
    cudaGetSymbolAddress((void**)&wi_hi, g_wi_hi); cudaGetSymbolAddress((void**)&wi_lo, g_wi_lo);
    cudaGetSymbolAddress((void**)&xc_hi, g_xc_hi); cudaGetSymbolAddress((void**)&xc_lo, g_xc_lo);
    cudaGetSymbolAddress((void**)&xp_hi, g_xp_hi); cudaGetSymbolAddress((void**)&xp_lo, g_xp_lo);
    cudaGetSymbolAddress((void**)&dta_hi,g_dta_hi);cudaGetSymbolAddress((void**)&dta_lo,g_dta_lo);
    cudaGetSymbolAddress((void**)&dtw_hi,g_dtw_hi);cudaGetSymbolAddress((void**)&dtw_lo,g_dtw_lo);
    cudaGetSymbolAddress((void**)&y_hi,  g_y_hi);  cudaGetSymbolAddress((void**)&y_lo,  g_y_lo);
    cudaGetSymbolAddress((void**)&ow_hi, g_ow_hi); cudaGetSymbolAddress((void**)&ow_lo, g_ow_lo);

    cudaFuncSetAttribute(tc_gemm, cudaFuncAttributeMaxDynamicSharedMemorySize, GSMEM);

    // 0) in_proj weight cvt
    {
        long t1 = (long)2 * DIM * DD;
        cvt_flat_kernel<<<(int)((t1 + 255) / 256), 256>>>(in_proj_w, t1, wi_hi, wi_lo);
    }
    // 1) remaining weights (fused)
    cvt_rest_kernel<<<(int)((C3 + 255) / 256), 256>>>(
        x_proj_w, dt_proj_w, out_proj_w,
        xp_hi, xp_lo, dtw_hi, dtw_lo, ow_hi, ow_lo);

    // 2) residual = x + residual; h = LN(residual) -> hi/lo
    addnorm_kernel<<<BL, 256>>>(x, residual, ln_w, ln_b, res_out, h_hi, h_lo);

    // 3) xz = h @ in_proj_w^T   (M=4096, N=4096, K=1024)   <-- ncu window
    tc_gemm<<<dim3(2 * DIM / 128, BL / 128), 256, GSMEM>>>(
        h_hi, h_lo, wi_hi, wi_lo, xz, 2 * DIM, 2 * DIM, DD, DD, 0,
        ((__nv_bfloat16*)0), ((__nv_bfloat16*)0), 0);

    // 4) xc = silu(causal_conv(x_in))
    conv_silu_kernel<<<(BB * LL * DIM + 255) / 256, 256>>>(xz, conv_w, conv_b, xc, xc_hi, xc_lo);

    // 5) x_dbl = xc @ x_proj_w^T (M=4096, N=96, K=2048), 8-way split-K + reduce
    tc_gemm<<<dim3(1, BL / 128, KSPL), 256, GSMEM>>>(
        xc_hi, xc_lo, xp_hi, xp_lo, xpart, NXD, NXD, DIM, DIM / KSPL,
        (long)BL * NXD, ((__nv_bfloat16*)0), ((__nv_bfloat16*)0), 0);
    xpart_reduce_kernel<<<(BL * NXD + 255) / 256, 256>>>(xpart, xdbl, dta_hi, dta_lo);

    // 6) dt_raw = dt_r @ dt_proj_w^T   (M=4096, N=2048, K=64)
    tc_gemm<<<dim3(DIM / 128, BL / 128), 256, GSMEM>>>(
        dta_hi, dta_lo, dtw_hi, dtw_lo, dtraw, DIM, DIM, DTRK, DTRK, 0,
        ((__nv_bfloat16*)0), ((__nv_bfloat16*)0), 0);

    // 7) chunked selective scan (pass1: local scans + dtv in-place;
    //    pass3: prefix combine + final scan + gate)
    scan_pass1<<<dim3(DIM / 128, NC, BB), 128>>>(
        xdbl, dtraw, dt_proj_b, xc, A_log, hend, Pbuf);
    scan_pass3<<<dim3(DIM / 128, NC, BB), 128>>>(
        xdbl, dtraw, xc, xz, A_log, D_param, hend, Pbuf, y_hi, y_lo);

    // 8) out = y @ out_proj_w^T   (M=4096, N=1024, K=2048)
    tc_gemm<<<dim3(DD / 128, BL / 128), 256, GSMEM>>>(
        y_hi, y_lo, ow_hi, ow_lo, out, DD, DD, DIM, DIM, 0,
        ((__nv_bfloat16*)0), ((__nv_bfloat16*)0), 0);
}

// round 10
// speedup vs baseline: 4.7879x; 1.0126x over previous
#include <cuda_runtime.h>
#include <cuda_bf16.h>
#include <cstdint>
#include <math.h>

// Problem constants
#define BB   2
#define LL   2048
#define DD   1024
#define DIM  2048      // d_inner
#define DS   16        // d_state
#define DTRK 64        // dt_rank
#define NXD  96        // DTR + 2*DS
#define BL   (BB*LL)   // 4096 rows
#define NC   16        // scan chunks
#define CS   (LL/NC)   // 128 steps per chunk
#define KSPL 8         // x_proj split-K factor

// ---------------- scratch (device globals; no runtime allocation) ----------
__device__ __align__(256) float g_xz[(size_t)BL * 2 * DIM];
__device__ __align__(256) float g_xc[(size_t)BL * DIM];
__device__ __align__(256) float g_xdbl[(size_t)BL * NXD];
__device__ __align__(256) float g_xpart[(size_t)KSPL * BL * NXD];
__device__ __align__(256) float g_dtraw[(size_t)BL * DIM];   // dt linear -> dtv (in-place)
__device__ __align__(256) float g_hend[(size_t)BB * NC * DS * DIM];
__device__ __align__(256) float g_P[(size_t)BB * NC * DS * DIM];

__device__ __align__(256) __nv_bfloat16 g_h_hi[(size_t)BL * DD],    g_h_lo[(size_t)BL * DD];
__device__ __align__(256) __nv_bfloat16 g_wi_hi[(size_t)2*DIM*DD],  g_wi_lo[(size_t)2*DIM*DD];
__device__ __align__(256) __nv_bfloat16 g_xc_hi[(size_t)BL * DIM],  g_xc_lo[(size_t)BL * DIM];
__device__ __align__(256) __nv_bfloat16 g_xp_hi[(size_t)NXD * DIM], g_xp_lo[(size_t)NXD * DIM];
__device__ __align__(256) __nv_bfloat16 g_dta_hi[(size_t)BL * DTRK],g_dta_lo[(size_t)BL * DTRK];
__device__ __align__(256) __nv_bfloat16 g_dtw_hi[(size_t)DIM*DTRK], g_dtw_lo[(size_t)DIM*DTRK];
__device__ __align__(256) __nv_bfloat16 g_y_hi[(size_t)BL * DIM],   g_y_lo[(size_t)BL * DIM];
__device__ __align__(256) __nv_bfloat16 g_ow_hi[(size_t)DD * DIM],  g_ow_lo[(size_t)DD * DIM];

// ---------------- helpers ----------------------------------------------------
__device__ __forceinline__ uint32_t smem_u32(const void* p) {
    uint32_t a;
    asm("{ .reg .u64 t; cvta.to.shared.u64 t, %1; cvt.u32.u64 %0, t; }"
        : "=r"(a) : "l"(p));
    return a;
}
__device__ __forceinline__ void split_bf16(float v, __nv_bfloat16& hi, __nv_bfloat16& lo) {
    hi = __float2bfloat16(v);
    lo = __float2bfloat16(v - __bfloat162float(hi));
}
__device__ __forceinline__ float softplus_f(float x) {
    return (x > 20.f) ? x : log1pf(__expf(x));
}
// powers E^1..E^16 via depth-4 tree (15 FMUL, crit path 4)
__device__ __forceinline__ void pow_tree(float E, float pw[DS]) {
    float E2 = E * E, E4 = E2 * E2, E8 = E4 * E4;
    pw[0] = E;        pw[1] = E2;       pw[2] = E2 * E;   pw[3] = E4;
    pw[4] = E4 * E;   pw[5] = E4 * E2;  pw[6] = E4 * pw[2]; pw[7] = E8;
    pw[8] = E8 * E;   pw[9] = E8 * E2;  pw[10] = E8 * pw[2]; pw[11] = E8 * E4;
    pw[12] = E8 * pw[4]; pw[13] = E8 * pw[5]; pw[14] = E8 * pw[6]; pw[15] = E8 * E8;
}

__device__ __forceinline__ void ldm_x4(uint32_t addr, uint32_t r[4]) {
    asm volatile("ldmatrix.sync.aligned.m8n8.x4.shared.b16 {%0,%1,%2,%3}, [%4];"
        : "=r"(r[0]), "=r"(r[1]), "=r"(r[2]), "=r"(r[3]) : "r"(addr));
}
__device__ __forceinline__ void mma_bf16(float d[4], const uint32_t a[4],
                                         uint32_t b0, uint32_t b1) {
    asm volatile(
        "mma.sync.aligned.m16n8k16.row.col.f32.bf16.bf16.f32 "
        "{%0,%1,%2,%3}, {%4,%5,%6,%7}, {%8,%9}, {%0,%1,%2,%3};"
        : "+f"(d[0]), "+f"(d[1]), "+f"(d[2]), "+f"(d[3])
        : "r"(a[0]), "r"(a[1]), "r"(a[2]), "r"(a[3]), "r"(b0), "r"(b1));
}
__device__ __forceinline__ void cp16(uint32_t dst, const void* src, int srcsize) {
    asm volatile("cp.async.cg.shared.global [%0], [%1], 16, %2;"
                 :: "r"(dst), "l"(src), "r"(srcsize));
}
__device__ __forceinline__ void cp_commit() {
    asm volatile("cp.async.commit_group;");
}
__device__ __forceinline__ void cp_wait2() {
    asm volatile("cp.async.wait_group 2;");
}

// ---------------- split-bf16 tensor-core GEMM (mma.sync path) ----------------
#define TILEB 8192                 // 128 rows * 64 B
#define STAGE3 (4 * TILEB)         // 32768 B per stage
#define GSMEM (3 * STAGE3)         // 98304 B dynamic smem

__global__ __launch_bounds__(256, 2) void tc_gemm(
    const __nv_bfloat16* __restrict__ Ahi, const __nv_bfloat16* __restrict__ Alo,
    const __nv_bfloat16* __restrict__ Bhi, const __nv_bfloat16* __restrict__ Blo,
    float* __restrict__ C, int ldc, int N, int ldK, int Ksub, long cstride,
    __nv_bfloat16* __restrict__ Ehi, __nv_bfloat16* __restrict__ Elo, int ecols)
{
    extern __shared__ char smem[];
    const uint32_t sbase = smem_u32(smem);
    const int tid  = threadIdx.x;
    const int wid  = tid >> 5;
    const int lane = tid & 31;
    const int warp_m = wid & 3;
    const int warp_n = wid >> 2;
    const int m0 = blockIdx.y * 128;
    const int n0 = blockIdx.x * 128;
    const int kbase = blockIdx.z * Ksub;
    C += (long)blockIdx.z * cstride;

    const __nv_bfloat16* srcA[2] = { Ahi + (size_t)m0 * ldK + kbase,
                                     Alo + (size_t)m0 * ldK + kbase };
    const __nv_bfloat16* srcB[2] = { Bhi + (size_t)n0 * ldK + kbase,
                                     Blo + (size_t)n0 * ldK + kbase };

    float acc[2][8][4];
    #pragma unroll
    for (int a = 0; a < 2; a++)
        #pragma unroll
        for (int b = 0; b < 8; b++)
            #pragma unroll
            for (int c = 0; c < 4; c++) acc[a][b][c] = 0.f;

    const int nch = Ksub / 32;

    auto load_chunk = [&](int stage, int k0) {
        const uint32_t base = sbase + stage * STAGE3;
        #pragma unroll
        for (int i = 0; i < 8; i++) {
            const int tile = i >> 1;
            const int rem  = ((i & 1) << 8) + tid;
            const int row  = rem >> 2;
            const int c    = rem & 3;
            const int csw  = c ^ ((row >> 1) & 3);
            const uint32_t dst = base + tile * TILEB + row * 64 + csw * 16;
            const __nv_bfloat16* g;
            int sz = 16;
            if (tile < 2) {
                g = srcA[tile] + (size_t)row * ldK + k0 + c * 8;
            } else {
                g = srcB[tile - 2] + (size_t)row * ldK + k0 + c * 8;
                if (n0 + row >= N) sz = 0;
            }
            cp16(dst, g, sz);
        }
    };

    load_chunk(0, 0);
    cp_commit();
    if (1 < nch) load_chunk(1, 32);
    cp_commit();

    for (int ch = 0; ch < nch; ch++) {
        if (ch + 2 < nch) load_chunk((ch + 2) % 3, (ch + 2) * 32);
        cp_commit();
        cp_wait2();
        __syncthreads();

        const uint32_t st = sbase + (ch % 3) * STAGE3;
        const uint32_t aHiB = st;
        const uint32_t aLoB = st + TILEB;
        const uint32_t bHiB = st + 2 * TILEB;
        const uint32_t bLoB = st + 3 * TILEB;

        #pragma unroll
        for (int k16 = 0; k16 < 2; k16++) {
            uint32_t ah[2][4], al[2][4], bh[4][4], bl[4][4];
            const int ci = k16 * 2 + (lane >> 4);
            // preload A fragments + first B fragment
            #pragma unroll
            for (int mf = 0; mf < 2; mf++) {
                const int row = warp_m * 32 + mf * 16 + (lane & 15);
                const uint32_t off = row * 64 + ((ci ^ ((row >> 1) & 3)) * 16);
                ldm_x4(aHiB + off, ah[mf]);
                ldm_x4(aLoB + off, al[mf]);
            }
            {
                const int rowb = warp_n * 64 + (lane & 15);
                const uint32_t offb = rowb * 64 + ((ci ^ ((rowb >> 1) & 3)) * 16);
                ldm_x4(bHiB + offb, bh[0]);
                ldm_x4(bLoB + offb, bl[0]);
            }
            // per-nb: issue 12 MMAs while loading B frags for nb+1
            #pragma unroll
            for (int nb = 0; nb < 4; nb++) {
                if (nb < 3) {
                    const int rowb = warp_n * 64 + (nb + 1) * 16 + (lane & 15);
                    const uint32_t offb = rowb * 64 + ((ci ^ ((rowb >> 1) & 3)) * 16);
                    ldm_x4(bHiB + offb, bh[nb + 1]);
                    ldm_x4(bLoB + offb, bl[nb + 1]);
                }
                // term 1: Ahi*Bhi
                mma_bf16(acc[0][nb*2],   ah[0], bh[nb][0], bh[nb][2]);
                mma_bf16(acc[0][nb*2+1], ah[0], bh[nb][1], bh[nb][3]);
                mma_bf16(acc[1][nb*2],   ah[1], bh[nb][0], bh[nb][2]);
                mma_bf16(acc[1][nb*2+1], ah[1], bh[nb][1], bh[nb][3]);
                // term 2: Ahi*Blo
                mma_bf16(acc[0][nb*2],   ah[0], bl[nb][0], bl[nb][2]);
                mma_bf16(acc[0][nb*2+1], ah[0], bl[nb][1], bl[nb][3]);
                mma_bf16(acc[1][nb*2],   ah[1], bl[nb][0], bl[nb][2]);
                mma_bf16(acc[1][nb*2+1], ah[1], bl[nb][1], bl[nb][3]);
                // term 3: Alo*Bhi
                mma_bf16(acc[0][nb*2],   al[0], bh[nb][0], bh[nb][2]);
                mma_bf16(acc[0][nb*2+1], al[0], bh[nb][1], bh[nb][3]);
                mma_bf16(acc[1][nb*2],   al[1], bh[nb][0], bh[nb][2]);
                mma_bf16(acc[1][nb*2+1], al[1], bh[nb][1], bh[nb][3]);
            }
        }
        __syncthreads();
    }

    #pragma unroll
    for (int mf = 0; mf < 2; mf++) {
        #pragma unroll
        for (int nf = 0; nf < 8; nf++) {
            const int r0  = m0 + warp_m * 32 + mf * 16 + (lane >> 2);
            const int col = n0 + warp_n * 64 + nf * 8 + (lane & 3) * 2;
            if (col < N) {
                float2 v0 = make_float2(acc[mf][nf][0], acc[mf][nf][1]);
                float2 v1 = make_float2(acc[mf][nf][2], acc[mf][nf][3]);
                *reinterpret_cast<float2*>(C + (size_t)r0 * ldc + col) = v0;
                *reinterpret_cast<float2*>(C + (size_t)(r0 + 8) * ldc + col) = v1;
                if (Ehi && col < ecols) {
                    __nv_bfloat16 h0, l0, h1, l1;
                    split_bf16(v0.x, h0, l0); split_bf16(v0.y, h1, l1);
                    __nv_bfloat162 hh = __nv_bfloat162(h0, h1);
                    __nv_bfloat162 ll = __nv_bfloat162(l0, l1);
                    *reinterpret_cast<__nv_bfloat162*>(Ehi + (size_t)r0 * ecols + col) = hh;
                    *reinterpret_cast<__nv_bfloat162*>(Elo + (size_t)r0 * ecols + col) = ll;
                    split_bf16(v1.x, h0, l0); split_bf16(v1.y, h1, l1);
                    hh = __nv_bfloat162(h0, h1); ll = __nv_bfloat162(l0, l1);
                    *reinterpret_cast<__nv_bfloat162*>(Ehi + (size_t)(r0+8) * ecols + col) = hh;
                    *reinterpret_cast<__nv_bfloat162*>(Elo + (size_t)(r0+8) * ecols + col) = ll;
                }
            }
        }
    }
}

// ---------------- split-K reduce for x_proj + fused dt-slice cvt -------------
__global__ __launch_bounds__(256) void xpart_reduce_kernel(
    const float* __restrict__ part, float* __restrict__ xdbl,
    __nv_bfloat16* __restrict__ dta_hi, __nv_bfloat16* __restrict__ dta_lo)
{
    int i = blockIdx.x * blockDim.x + threadIdx.x;
    if (i >= BL * NXD) return;
    float s = 0.f;
    #pragma unroll
    for (int z = 0; z < KSPL; z++) s += part[(size_t)z * BL * NXD + i];
    xdbl[i] = s;
    int col = i % NXD;
    if (col < DTRK) {
        int row = i / NXD;
        __nv_bfloat16 h, l; split_bf16(s, h, l);
        dta_hi[(size_t)row * DTRK + col] = h;
        dta_lo[(size_t)row * DTRK + col] = l;
    }
}

// ---------------- weight conversions ----------------------------------------
__global__ __launch_bounds__(256) void cvt_flat_kernel(
    const float* __restrict__ src, long total,
    __nv_bfloat16* __restrict__ hi, __nv_bfloat16* __restrict__ lo)
{
    long i = (long)blockIdx.x * blockDim.x + threadIdx.x;
    if (i >= total) return;
    __nv_bfloat16 h, l; split_bf16(src[i], h, l);
    hi[i] = h; lo[i] = l;
}

#define C1 ((long)NXD * DIM)
#define C2 (C1 + (long)DIM * DTRK)
#define C3 (C2 + (long)DD * DIM)
__global__ __launch_bounds__(256) void cvt_rest_kernel(
    const float* __restrict__ s0, const float* __restrict__ s1,
    const float* __restrict__ s2,
    __nv_bfloat16* __restrict__ h0, __nv_bfloat16* __restrict__ l0,
    __nv_bfloat16* __restrict__ h1, __nv_bfloat16* __restrict__ l1,
    __nv_bfloat16* __restrict__ h2, __nv_bfloat16* __restrict__ l2)
{
    long i = (long)blockIdx.x * blockDim.x + threadIdx.x;
    if (i >= C3) return;
    const float* s; __nv_bfloat16 *ph, *pl; long j;
    if (i < C1)      { s = s0; ph = h0; pl = l0; j = i; }
    else if (i < C2) { s = s1; ph = h1; pl = l1; j = i - C1; }
    else             { s = s2; ph = h2; pl = l2; j = i - C2; }
    __nv_bfloat16 h, l; split_bf16(s[j], h, l);
    ph[j] = h; pl[j] = l;
}

// ---------------- fused add + LayerNorm (emits residual + h hi/lo) ----------
__global__ __launch_bounds__(256) void addnorm_kernel(
    const float* __restrict__ x, const float* __restrict__ res,
    const float* __restrict__ w, const float* __restrict__ b,
    float* __restrict__ res_out,
    __nv_bfloat16* __restrict__ h_hi, __nv_bfloat16* __restrict__ h_lo)
{
    const int row = blockIdx.x;
    const int tid = threadIdx.x;
    const float4* xv = reinterpret_cast<const float4*>(x + (size_t)row * DD);
    const float4* rv = reinterpret_cast<const float4*>(res + (size_t)row * DD);
    float4 a = xv[tid], r = rv[tid];
    float4 v = make_float4(a.x + r.x, a.y + r.y, a.z + r.z, a.w + r.w);
    reinterpret_cast<float4*>(res_out + (size_t)row * DD)[tid] = v;

    float s  = v.x + v.y + v.z + v.w;
    float ss = v.x*v.x + v.y*v.y + v.z*v.z + v.w*v.w;
    __shared__ float red[16];
    #pragma unroll
    for (int o = 16; o > 0; o >>= 1) {
        s  += __shfl_xor_sync(0xFFFFFFFFu, s,  o);
        ss += __shfl_xor_sync(0xFFFFFFFFu, ss, o);
    }
    int wid = tid >> 5, lane = tid & 31;
    if (lane == 0) { red[wid] = s; red[8 + wid] = ss; }
    __syncthreads();
    if (tid == 0) {
        float ts = 0.f, tss = 0.f;
        #pragma unroll
        for (int i = 0; i < 8; i++) { ts += red[i]; tss += red[8 + i]; }
        float mean = ts * (1.f / DD);
        float var  = tss * (1.f / DD) - mean * mean;
        red[0] = mean; red[1] = rsqrtf(var + 1e-5f);
    }
    __syncthreads();
    float mean = red[0], rstd = red[1];
    float4 wv = reinterpret_cast<const float4*>(w)[tid];
    float4 bv = reinterpret_cast<const float4*>(b)[tid];
    float hv[4];
    hv[0] = (v.x - mean) * rstd * wv.x + bv.x;
    hv[1] = (v.y - mean) * rstd * wv.y + bv.y;
    hv[2] = (v.z - mean) * rstd * wv.z + bv.z;
    hv[3] = (v.w - mean) * rstd * wv.w + bv.w;
    __nv_bfloat16 hh[4], ll[4];
    #pragma unroll
    for (int i = 0; i < 4; i++) split_bf16(hv[i], hh[i], ll[i]);
    size_t o = (size_t)row * DD + tid * 4;
    *reinterpret_cast<uint2*>(h_hi + o) = *reinterpret_cast<uint2*>(hh);
    *reinterpret_cast<uint2*>(h_lo + o) = *reinterpret_cast<uint2*>(ll);
}

// ---------------- causal depthwise conv (DC=4) + SiLU ------------------------
__global__ __launch_bounds__(256) void conv_silu_kernel(
    const float* __restrict__ xz, const float* __restrict__ cw,
    const float* __restrict__ cb, float* __restrict__ xc,
    __nv_bfloat16* __restrict__ xc_hi, __nv_bfloat16* __restrict__ xc_lo)
{
    int idx = blockIdx.x * blockDim.x + threadIdx.x;
    if (idx >= BB * LL * DIM) return;
    int d = idx % DIM;
    int t = (idx / DIM) % LL;
    int b = idx / (DIM * LL);
    float w0 = cw[d * 4 + 0], w1 = cw[d * 4 + 1];
    float w2 = cw[d * 4 + 2], w3 = cw[d * 4 + 3];
    size_t base = ((size_t)(b * LL + t)) * (2 * DIM) + d;
    float acc = cb[d];
    if (t >= 3) acc = fmaf(xz[base - 3 * (size_t)(2 * DIM)], w0, acc);
    if (t >= 2) acc = fmaf(xz[base - 2 * (size_t)(2 * DIM)], w1, acc);
    if (t >= 1) acc = fmaf(xz[base - 1 * (size_t)(2 * DIM)], w2, acc);
    acc = fmaf(xz[base], w3, acc);
    float sg = 1.f / (1.f + __expf(-acc));
    float v = acc * sg;
    xc[idx] = v;
    __nv_bfloat16 h, l; split_bf16(v, h, l);
    xc_hi[idx] = h; xc_lo[idx] = l;
}

// ---------------- chunked selective scan --------------------------------------
// S4D structure: A_log rows are log(1..16) -> a[s]=-(s+1); exp(dt*a[s]) = E^(s+1)
// with E=exp(-dt), powers built via depth-4 tree. Per-thread pow_ok check with
// generic fallback. pass1 stores dtv in-place; pass3 does its own prefix combine.
#define CH 32

__global__ __launch_bounds__(128) void scan_pass1(
    const float* __restrict__ xdbl, float* __restrict__ dtraw,
    const float* __restrict__ dtb, const float* __restrict__ xc,
    const float* __restrict__ A_log,
    float* __restrict__ hend, float* __restrict__ Pbuf)
{
    const int b = blockIdx.z, c = blockIdx.y;
    const int d = blockIdx.x * 128 + threadIdx.x;
    float a[DS], h[DS];
    bool pow_ok = true;
    #pragma unroll
    for (int s = 0; s < DS; s++) {
        a[s] = -__expf(A_log[(size_t)d * DS + s]);
        pow_ok = pow_ok && (fabsf(-a[s] - (float)(s + 1)) < 1e-3f);
        h[s] = 0.f;
    }
    const float bias = dtb[d];
    float sumdt = 0.f;
    __shared__ float sB[CH][DS];
    const int tbase = c * CS;

    for (int t0 = 0; t0 < CS; t0 += CH) {
        __syncthreads();
        for (int idx = threadIdx.x; idx < CH * DS; idx += 128) {
            int r = idx >> 4, col = idx & 15;
            sB[r][col] = xdbl[(size_t)(b * LL + tbase + t0 + r) * NXD + DTRK + col];
        }
        __syncthreads();
        if (pow_ok) {
            #pragma unroll 4
            for (int r = 0; r < CH; r++) {
                size_t off = (size_t)(b * LL + tbase + t0 + r) * DIM + d;
                float dtv = softplus_f(dtraw[off] + bias);
                dtraw[off] = dtv;
                sumdt += dtv;
                float dtx = dtv * xc[off];
                float pw[DS];
                pow_tree(__expf(-dtv), pw);
                #pragma unroll
                for (int s = 0; s < DS; s++)
                    h[s] = fmaf(pw[s], h[s], dtx * sB[r][s]);
            }
        } else {
            #pragma unroll 4
            for (int r = 0; r < CH; r++) {
                size_t off = (size_t)(b * LL + tbase + t0 + r) * DIM + d;
                float dtv = softplus_f(dtraw[off] + bias);
                dtraw[off] = dtv;
                sumdt += dtv;
                float dtx = dtv * xc[off];
                #pragma unroll
                for (int s = 0; s < DS; s++)
                    h[s] = fmaf(__expf(dtv * a[s]), h[s], dtx * sB[r][s]);
            }
        }
    }
    size_t obase = ((size_t)(b * NC + c) * DS) * DIM + d;
    if (pow_ok) {
        float pw[DS];
        pow_tree(__expf(-sumdt), pw);
        #pragma unroll
        for (int s = 0; s < DS; s++) {
            hend[obase + (size_t)s * DIM] = h[s];
            Pbuf[obase + (size_t)s * DIM] = pw[s];
        }
    } else {
        #pragma unroll
        for (int s = 0; s < DS; s++) {
            hend[obase + (size_t)s * DIM] = h[s];
            Pbuf[obase + (size_t)s * DIM] = __expf(a[s] * sumdt);
        }
    }
}

__global__ __launch_bounds__(128) void scan_pass3(
    const float* __restrict__ xdbl, const float* __restrict__ dtv_buf,
    const float* __restrict__ xc, const float* __restrict__ xz,
    const float* __restrict__ A_log, const float* __restrict__ Dp,
    const float* __restrict__ hend, const float* __restrict__ Pbuf,
    __nv_bfloat16* __restrict__ y_hi, __nv_bfloat16* __restrict__ y_lo)
{
    const int b = blockIdx.z, c = blockIdx.y;
    const int d = blockIdx.x * 128 + threadIdx.x;
    float a[DS], h[DS];
    bool pow_ok = true;
    #pragma unroll
    for (int s = 0; s < DS; s++) {
        a[s] = -__expf(A_log[(size_t)d * DS + s]);
        pow_ok = pow_ok && (fabsf(-a[s] - (float)(s + 1)) < 1e-3f);
        h[s] = 0.f;
    }
    for (int cc = 0; cc < c; cc++) {
        size_t base = ((size_t)(b * NC + cc) * DS) * DIM + d;
        #pragma unroll
        for (int s = 0; s < DS; s++)
            h[s] = fmaf(Pbuf[base + (size_t)s * DIM], h[s],
                        hend[base + (size_t)s * DIM]);
    }
    const float Dd = Dp[d];
    __shared__ float sB[CH][DS];
    __shared__ float sC[CH][DS];
    const int tbase = c * CS;

    for (int t0 = 0; t0 < CS; t0 += CH) {
        __syncthreads();
        for (int idx = threadIdx.x; idx < CH * 32; idx += 128) {
            int r = idx >> 5, col = idx & 31;
            float v = xdbl[(size_t)(b * LL + tbase + t0 + r) * NXD + DTRK + col];
            if (col < DS) sB[r][col] = v; else sC[r][col - DS] = v;
        }
        __syncthreads();
        if (pow_ok) {
            #pragma unroll 4
            for (int r = 0; r < CH; r++) {
                int t = tbase + t0 + r;
                size_t off = (size_t)(b * LL + t) * DIM + d;
                float dtv = dtv_buf[off];
                float x = xc[off];
                float z = xz[(size_t)(b * LL + t) * (2 * DIM) + DIM + d];
                float dtx = dtv * x;
                float y = 0.f;
                float pw[DS];
                pow_tree(__expf(-dtv), pw);
                #pragma unroll
                for (int s = 0; s < DS; s++) {
                    h[s] = fmaf(pw[s], h[s], dtx * sB[r][s]);
                    y = fmaf(h[s], sC[r][s], y);
                }
                float sz = z / (1.f + __expf(-z));
                float yo = (y + Dd * x) * sz;
                __nv_bfloat16 hh, ll; split_bf16(yo, hh, ll);
                y_hi[off] = hh; y_lo[off] = ll;
            }
        } else {
            #pragma unroll 4
            for (int r = 0; r < CH; r++) {
                int t = tbase + t0 + r;
                size_t off = (size_t)(b * LL + t) * DIM + d;
                float dtv = dtv_buf[off];
                float x = xc[off];
                float z = xz[(size_t)(b * LL + t) * (2 * DIM) + DIM + d];
                float dtx = dtv * x;
                float y = 0.f;
                #pragma unroll
                for (int s = 0; s < DS; s++) {
                    h[s] = fmaf(__expf(dtv * a[s]), h[s], dtx * sB[r][s]);
                    y = fmaf(h[s], sC[r][s], y);
                }
                float sz = z / (1.f + __expf(-z));
                float yo = (y + Dd * x) * sz;
                __nv_bfloat16 hh, ll; split_bf16(yo, hh, ll);
                y_hi[off] = hh; y_lo[off] = ll;
            }
        }
    }
}

// ---------------- launch ------------------------------------------------------
extern "C" void kernel_launch(void* const* d_in, const int* in_sizes, int n_in,
                              void* d_out, int out_size)
{
    const float* x          = (const float*)d_in[0];
    const float* residual   = (const float*)d_in[1];
    const float* ln_w       = (const float*)d_in[2];
    const float* ln_b       = (const float*)d_in[3];
    const float* in_proj_w  = (const float*)d_in[4];
    const float* conv_w     = (const float*)d_in[5];
    const float* conv_b     = (const float*)d_in[6];
    const float* x_proj_w   = (const float*)d_in[7];
    const float* dt_proj_w  = (const float*)d_in[8];
    const float* dt_proj_b  = (const float*)d_in[9];
    const float* A_log      = (const float*)d_in[10];
    const float* D_param    = (const float*)d_in[11];
    const float* out_proj_w = (const float*)d_in[12];

    float* out     = (float*)d_out;
    float* res_out = out + (size_t)BL * DD;

    float *xz, *xc, *xdbl, *xpart, *dtraw, *hend, *Pbuf;
    __nv_bfloat16 *h_hi, *h_lo, *wi_hi, *wi_lo, *xc_hi, *xc_lo, *xp_hi, *xp_lo;
    __nv_bfloat16 *dta_hi, *dta_lo, *dtw_hi, *dtw_lo, *y_hi, *y_lo, *ow_hi, *ow_lo;
    cudaGetSymbolAddress((void**)&xz,    g_xz);
    cudaGetSymbolAddress((void**)&xc,    g_xc);
    cudaGetSymbolAddress((void**)&xdbl,  g_xdbl);
    cudaGetSymbolAddress((void**)&xpart, g_xpart);
    cudaGetSymbolAddress((void**)&dtraw, g_dtraw);
    cudaGetSymbolAddress((void**)&hend,  g_hend);
    cudaGetSymbolAddress((void**)&Pbuf,  g_P);
    cudaGetSymbolAddress((void**)&h_hi,  g_h_hi);  cudaGetSymbolAddress((void**)&h_lo,  g_h_lo);
    cudaGetSymbolAddress((void**)&wi_hi, g_wi_hi); cudaGetSymbolAddress((void**)&wi_lo, g_wi_lo);
    cudaGetSymbolAddress((void**)&xc_hi, g_xc_hi); cudaGetSymbolAddress((void**)&xc_lo, g_xc_lo);
    cudaGetSymbolAddress((void**)&xp_hi, g_xp_hi); cudaGetSymbolAddress((void**)&xp_lo, g_xp_lo);
    cudaGetSymbolAddress((void**)&dta_hi,g_dta_hi);cudaGetSymbolAddress((void**)&dta_lo,g_dta_lo);
    cudaGetSymbolAddress((void**)&dtw_hi,g_dtw_hi);cudaGetSymbolAddress((void**)&dtw_lo,g_dtw_lo);
    cudaGetSymbolAddress((void**)&y_hi,  g_y_hi);  cudaGetSymbolAddress((void**)&y_lo,  g_y_lo);
    cudaGetSymbolAddress((void**)&ow_hi, g_ow_hi); cudaGetSymbolAddress((void**)&ow_lo, g_ow_lo);

    cudaFuncSetAttribute(tc_gemm, cudaFuncAttributeMaxDynamicSharedMemorySize, GSMEM);

    // 0) in_proj weight cvt
    {
        long t1 = (long)2 * DIM * DD;
        cvt_flat_kernel<<<(int)((t1 + 255) / 256), 256>>>(in_proj_w, t1, wi_hi, wi_lo);
    }
    // 1) remaining weights (fused)
    cvt_rest_kernel<<<(int)((C3 + 255) / 256), 256>>>(
        x_proj_w, dt_proj_w, out_proj_w,
        xp_hi, xp_lo, dtw_hi, dtw_lo, ow_hi, ow_lo);

    // 2) residual = x + residual; h = LN(residual) -> hi/lo
    addnorm_kernel<<<BL, 256>>>(x, residual, ln_w, ln_b, res_out, h_hi, h_lo);

    // 3) xz = h @ in_proj_w^T   (M=4096, N=4096, K=1024)   <-- ncu window
    tc_gemm<<<dim3(2 * DIM / 128, BL / 128), 256, GSMEM>>>(
        h_hi, h_lo, wi_hi, wi_lo, xz, 2 * DIM, 2 * DIM, DD, DD, 0,
        ((__nv_bfloat16*)0), ((__nv_bfloat16*)0), 0);

    // 4) xc = silu(causal_conv(x_in))
    conv_silu_kernel<<<(BB * LL * DIM + 255) / 256, 256>>>(xz, conv_w, conv_b, xc, xc_hi, xc_lo);

    // 5) x_dbl = xc @ x_proj_w^T (M=4096, N=96, K=2048), 8-way split-K + reduce
    tc_gemm<<<dim3(1, BL / 128, KSPL), 256, GSMEM>>>(
        xc_hi, xc_lo, xp_hi, xp_lo, xpart, NXD, NXD, DIM, DIM / KSPL,
        (long)BL * NXD, ((__nv_bfloat16*)0), ((__nv_bfloat16*)0), 0);
    xpart_reduce_kernel<<<(BL * NXD + 255) / 256, 256>>>(xpart, xdbl, dta_hi, dta_lo);

    // 6) dt_raw = dt_r @ dt_proj_w^T   (M=4096, N=2048, K=64)
    tc_gemm<<<dim3(DIM / 128, BL / 128), 256, GSMEM>>>(
        dta_hi, dta_lo, dtw_hi, dtw_lo, dtraw, DIM, DIM, DTRK, DTRK, 0,
        ((__nv_bfloat16*)0), ((__nv_bfloat16*)0), 0);

    // 7) chunked selective scan
    scan_pass1<<<dim3(DIM / 128, NC, BB), 128>>>(
        xdbl, dtraw, dt_proj_b, xc, A_log, hend, Pbuf);
    scan_pass3<<<dim3(DIM / 128, NC, BB), 128>>>(
        xdbl, dtraw, xc, xz, A_log, D_param, hend, Pbuf, y_hi, y_lo);

    // 8) out = y @ out_proj_w^T   (M=4096, N=1024, K=2048)
    tc_gemm<<<dim3(DD / 128, BL / 128), 256, GSMEM>>>(
        y_hi, y_lo, ow_hi, ow_lo, out, DD, DD, DIM, DIM, 0,
        ((__nv_bfloat16*)0), ((__nv_bfloat16*)0), 0);
}